// round 6
// baseline (speedup 1.0000x reference)
#include <cuda_runtime.h>
#include <math.h>
#include <stdint.h>

#define R        2048
#define KCLS     20
#define NSC      21
#define IMGW     1333.0f
#define IMGH     800.0f
#define SCORE_TH 0.5f
#define NMS_TH   0.5f
#define TOPK     100
#define NEG_INF  __int_as_float(0xFF800000)

// ---------------- global scratch (tiny) ----------------
__device__ unsigned long long g_kept[KCLS * TOPK];  // merged keys per class, desc
__device__ int                g_kcnt[KCLS];
__device__ int                g_done = 0;

__device__ __forceinline__ unsigned int fkey(float f) {
    unsigned int u = __float_as_uint(f);
    return (u & 0x80000000u) ? ~u : (u | 0x80000000u);
}
__device__ __forceinline__ float fkey_inv(unsigned int k) {
    unsigned int bits = (k & 0x80000000u) ? (k ^ 0x80000000u) : ~k;
    return __uint_as_float(bits);
}

// shared memory layout (dynamic)
#define OFF_SKEY   0          // u64[2048]          16384
#define OFF_SBOX   16384      // f32[4*2048]        32768
#define OFF_SAREA  49152      // f32[2048]           8192
#define OFF_KX1    57344      // f32[2048]           8192
#define OFF_KY1    65536
#define OFF_KX2    73728
#define OFF_KY2    81920
#define OFF_KAREA  90112
#define OFF_VALPRE 98304      // u8[2048]            2048
#define OFF_SVAL   100352     // u32[64]              256
#define OFF_DWLO   100608     // u32[64]              256
#define OFF_DWHI   100864     // u32[64]              256
#define OFF_MISC   101120     // suppW[2], smax, snk   16
#define SMEM_BYTES 101376
// merge-phase reuse (CTA 0 only, after NMS): sKeys u64[2000] @0,
// outk u64[100] @16000, scnt int[20] @16800, stot @16880

__device__ __forceinline__ float iou_gt(float x1, float y1, float x2, float y2,
                                        float a, float cx1, float cy1,
                                        float cx2, float cy2, float ca) {
    float xx1 = fmaxf(x1, cx1);
    float yy1 = fmaxf(y1, cy1);
    float xx2 = fminf(x2, cx2);
    float yy2 = fminf(y2, cy2);
    float w = fmaxf(xx2 - xx1, 0.0f);
    float h = fmaxf(yy2 - yy1, 0.0f);
    float inter = w * h;
    float uni = a + ca - inter;
    return inter / fmaxf(uni, 1e-9f);
}

__global__ void __launch_bounds__(1024, 1)
fused_nms_kernel(const float* __restrict__ boxes,
                 const float* __restrict__ scores,
                 float* __restrict__ out)
{
    extern __shared__ unsigned char smem[];
    unsigned long long* skey  = (unsigned long long*)(smem + OFF_SKEY);
    float* sx1   = (float*)(smem + OFF_SBOX);
    float* sy1   = sx1 + R;
    float* sx2   = sy1 + R;
    float* sy2   = sx2 + R;
    float* sarea = (float*)(smem + OFF_SAREA);
    float* kx1   = (float*)(smem + OFF_KX1);
    float* ky1   = (float*)(smem + OFF_KY1);
    float* kx2   = (float*)(smem + OFF_KX2);
    float* ky2   = (float*)(smem + OFF_KY2);
    float* karea = (float*)(smem + OFF_KAREA);
    unsigned char* valpre = (unsigned char*)(smem + OFF_VALPRE);
    unsigned int*  sval   = (unsigned int*)(smem + OFF_SVAL);
    unsigned int*  dwlo   = (unsigned int*)(smem + OFF_DWLO);
    unsigned int*  dwhi   = (unsigned int*)(smem + OFF_DWHI);
    unsigned int*  suppW  = (unsigned int*)(smem + OFF_MISC);
    int* smax = (int*)(smem + OFF_MISC + 8);
    int* snk  = (int*)(smem + OFF_MISC + 12);

    const int c    = blockIdx.x;
    const int t    = threadIdx.x;
    const int lane = t & 31;
    const int wid  = t >> 5;

    if (t == 0) { *smax = -1; *snk = 0; }

    // ---- phase 1: keys + validity ----
    for (int r = t; r < R; r += 1024) {
        bool fin = true;
        #pragma unroll
        for (int q = 0; q < 4; q++) fin &= isfinite(boxes[r * 4 + q]);
        for (int q = 0; q < NSC; q++) fin &= isfinite(scores[r * NSC + q]);
        float s = scores[r * NSC + c];
        valpre[r] = (fin && (s > SCORE_TH)) ? 1 : 0;
        skey[r] = ((unsigned long long)fkey(s) << 32) |
                  (unsigned long long)(0xFFFFFFFFu - (unsigned)r);
    }
    __syncthreads();

    // ---- phase 2: bitonic sort, descending (ties -> smaller r first) ----
    for (unsigned int kk = 2; kk <= (unsigned)R; kk <<= 1) {
        for (unsigned int j = kk >> 1; j > 0; j >>= 1) {
            #pragma unroll
            for (int e = 0; e < 2; e++) {
                unsigned int i = (unsigned)t + (unsigned)e * 1024u;
                unsigned int ixj = i ^ j;
                if (ixj > i) {
                    unsigned long long a = skey[i], b = skey[ixj];
                    bool descBlock = ((i & kk) == 0);
                    if (descBlock ? (a < b) : (a > b)) { skey[i] = b; skey[ixj] = a; }
                }
            }
            __syncthreads();
        }
    }

    // ---- phase 3: gather sorted clipped boxes + validity words + bound ----
    #pragma unroll
    for (int e = 0; e < 2; e++) {
        int i = t + e * 1024;
        unsigned long long key = skey[i];
        unsigned int rr = 0xFFFFFFFFu - (unsigned int)(key & 0xFFFFFFFFull);
        float x1 = fminf(fmaxf(boxes[rr * 4 + 0], 0.0f), IMGW);
        float y1 = fminf(fmaxf(boxes[rr * 4 + 1], 0.0f), IMGH);
        float x2 = fminf(fmaxf(boxes[rr * 4 + 2], 0.0f), IMGW);
        float y2 = fminf(fmaxf(boxes[rr * 4 + 3], 0.0f), IMGH);
        sx1[i] = x1; sy1[i] = y1; sx2[i] = x2; sy2[i] = y2;
        sarea[i] = (x2 - x1) * (y2 - y1);
        bool v = valpre[rr] != 0;
        if (v) atomicMax(smax, i);
        unsigned int ball = __ballot_sync(0xFFFFFFFFu, v);
        if (lane == 0) sval[i >> 5] = ball;
    }
    __syncthreads();

    const int sm = *smax;
    const int wcap = (sm < 0) ? 0 : ((sm >> 6) + 1);

    // ---- phase 4: chunked on-the-fly NMS ----
    for (int ch = 0; ch < wcap; ch++) {
        unsigned int vw0 = sval[2 * ch], vw1 = sval[2 * ch + 1];
        if ((vw0 | vw1) == 0u) continue;          // uniform skip

        if (t < 2) suppW[t] = 0u;
        int nk = *snk;
        __syncthreads();

        // (a) suppressed-by-existing-kept, 64 candidates across 32 warps x2
        #pragma unroll
        for (int half = 0; half < 2; half++) {
            int cand = (ch << 6) + wid + (half << 5);
            bool loc = false;
            if (cand <= sm) {
                float x1 = sx1[cand], y1 = sy1[cand];
                float x2 = sx2[cand], y2 = sy2[cand];
                float a = sarea[cand];
                for (int m = lane; m < nk; m += 32)
                    loc |= (iou_gt(x1, y1, x2, y2, a,
                                   kx1[m], ky1[m], kx2[m], ky2[m], karea[m])
                            > NMS_TH);
            }
            bool sup = __any_sync(0xFFFFFFFFu, loc);
            if (lane == 0 && sup) atomicOr(&suppW[half], 1u << wid);
        }

        // (b) 64x64 diagonal IoU words
        #pragma unroll
        for (int half = 0; half < 2; half++) {
            int cand = (ch << 6) + wid + (half << 5);
            float x1 = sx1[cand], y1 = sy1[cand];
            float x2 = sx2[cand], y2 = sy2[cand];
            float a = sarea[cand];
            int c0 = (ch << 6) + lane;
            int c1 = c0 + 32;
            bool blo = iou_gt(x1, y1, x2, y2, a,
                              sx1[c0], sy1[c0], sx2[c0], sy2[c0], sarea[c0]) > NMS_TH;
            bool bhi = iou_gt(x1, y1, x2, y2, a,
                              sx1[c1], sy1[c1], sx2[c1], sy2[c1], sarea[c1]) > NMS_TH;
            unsigned int rlo = __ballot_sync(0xFFFFFFFFu, blo);
            unsigned int rhi = __ballot_sync(0xFFFFFFFFu, bhi);
            if (lane == 0) {
                dwlo[wid + (half << 5)] = rlo;
                dwhi[wid + (half << 5)] = rhi;
            }
        }
        __syncthreads();

        // (c) warp 0: in-register greedy + append kept
        if (wid == 0) {
            unsigned long long pend =
                (((unsigned long long)vw1 << 32) | vw0) &
                ~(((unsigned long long)suppW[1] << 32) | (unsigned long long)suppW[0]);
            unsigned long long d0 = (unsigned long long)dwlo[lane] |
                                    ((unsigned long long)dwhi[lane] << 32);
            unsigned long long d1 = (unsigned long long)dwlo[32 + lane] |
                                    ((unsigned long long)dwhi[32 + lane] << 32);
            unsigned long long cur = pend, kept = 0ull;
            while (cur) {
                int b = __ffsll((unsigned long long)cur) - 1;
                kept |= 1ull << b;
                unsigned long long w0 = __shfl_sync(0xFFFFFFFFu, d0, b & 31);
                unsigned long long w1 = __shfl_sync(0xFFFFFFFFu, d1, b & 31);
                unsigned long long dw = (b < 32) ? w0 : w1;
                cur &= ~(1ull << b);
                cur &= ~dw;
            }
            // distribute appends across lanes, ascending bit order
            unsigned long long tk = kept;
            int idx = 0;
            while (tk) {
                int b = __ffsll((unsigned long long)tk) - 1;
                tk &= tk - 1;
                if ((idx & 31) == lane) {
                    int j = (ch << 6) + b;
                    int pos = nk + idx;
                    kx1[pos] = sx1[j]; ky1[pos] = sy1[j];
                    kx2[pos] = sx2[j]; ky2[pos] = sy2[j];
                    karea[pos] = sarea[j];
                    if (pos < TOPK) {
                        unsigned long long key = skey[j];
                        unsigned int rr = 0xFFFFFFFFu -
                            (unsigned int)(key & 0xFFFFFFFFull);
                        unsigned int flat = (unsigned)c * R + rr;
                        g_kept[c * TOPK + pos] =
                            (key & 0xFFFFFFFF00000000ull) |
                            (unsigned long long)(0xFFFFFFFFu - flat);
                    }
                }
                idx++;
            }
            if (lane == 0) *snk = nk + idx;
        }
        __syncthreads();
    }

    if (t == 0) {
        int n = *snk; if (n > TOPK) n = TOPK;
        g_kcnt[c] = n;
    }
    __threadfence();
    __syncthreads();
    if (t == 0) atomicAdd(&g_done, 1);

    if (c != 0) return;

    // ================= CTA 0: wait for all classes, then merge =============
    if (t == 0) {
        while (atomicAdd(&g_done, 0) != KCLS) { }
        g_done = 0;                       // reset for next graph replay
        __threadfence();
    }
    __syncthreads();

    unsigned long long* sKeys = (unsigned long long*)(smem + 0);      // [2000]
    unsigned long long* outk  = (unsigned long long*)(smem + 16000);  // [100]
    int* scnt = (int*)(smem + 16800);                                 // [20]
    int* stot = (int*)(smem + 16880);

    if (t < KCLS) scnt[t] = g_kcnt[t];
    __syncthreads();

    for (int e = t; e < KCLS * TOPK; e += 1024) {
        int cc = e / TOPK, p = e % TOPK;
        sKeys[e] = (p < scnt[cc]) ? g_kept[e] : 0ull;
    }
    if (t == 0) {
        int s = 0;
        for (int cc = 0; cc < KCLS; cc++) s += scnt[cc];
        *stot = s;
    }
    __syncthreads();

    // parallel rank selection
    for (int e = t; e < KCLS * TOPK; e += 1024) {
        int cc = e / TOPK, p = e % TOPK;
        if (p >= scnt[cc]) continue;
        unsigned long long key = sKeys[e];
        int rank = p;
        #pragma unroll
        for (int c2 = 0; c2 < KCLS; c2++) {
            if (c2 == cc) continue;
            int lo = 0, hi = scnt[c2];
            while (lo < hi) {
                int mid = (lo + hi) >> 1;
                if (sKeys[c2 * TOPK + mid] > key) lo = mid + 1; else hi = mid;
            }
            rank += lo;
            if (rank >= TOPK) break;
        }
        if (rank < TOPK) outk[rank] = key;
    }
    __syncthreads();

    // degenerate fallback: fewer than TOPK kept -> -inf entries, lowest
    // non-kept flat index first (matches lax.top_k over the masked matrix)
    if (t == 0 && *stot < TOPK) {
        int fill = *stot;
        int flat = 0;
        while (fill < TOPK) {
            int cc = flat >> 11;
            int n = scnt[cc];
            bool is_kept = false;
            for (int q = 0; q < n; q++) {
                unsigned int f2 = 0xFFFFFFFFu -
                    (unsigned int)(sKeys[cc * TOPK + q] & 0xFFFFFFFFull);
                if ((int)f2 == flat) { is_kept = true; break; }
            }
            if (!is_kept) {
                outk[fill] = ((unsigned long long)fkey(NEG_INF) << 32) |
                             (unsigned long long)(0xFFFFFFFFu - (unsigned)flat);
                fill++;
            }
            flat++;
        }
    }
    __syncthreads();

    if (t < TOPK) {
        unsigned long long key = outk[t];
        unsigned int flat = 0xFFFFFFFFu - (unsigned int)(key & 0xFFFFFFFFull);
        float sc = fkey_inv((unsigned int)(key >> 32));
        int cls = (int)(flat >> 11);      // R = 2048 = 2^11
        int rr  = (int)(flat & 2047u);
        out[t] = sc;
        out[TOPK + t * 4 + 0] = fminf(fmaxf(boxes[rr * 4 + 0], 0.0f), IMGW);
        out[TOPK + t * 4 + 1] = fminf(fmaxf(boxes[rr * 4 + 1], 0.0f), IMGH);
        out[TOPK + t * 4 + 2] = fminf(fmaxf(boxes[rr * 4 + 2], 0.0f), IMGW);
        out[TOPK + t * 4 + 3] = fminf(fmaxf(boxes[rr * 4 + 3], 0.0f), IMGH);
        out[TOPK + TOPK * 4 + t]        = (float)cls;
        out[TOPK + TOPK * 4 + TOPK + t] = (float)rr;
    }
}

extern "C" void kernel_launch(void* const* d_in, const int* in_sizes, int n_in,
                              void* d_out, int out_size)
{
    const float* boxes  = (const float*)d_in[0];   // [2048,4]
    const float* scores = (const float*)d_in[1];   // [2048,21]
    float* out = (float*)d_out;

    cudaFuncSetAttribute(fused_nms_kernel,
                         cudaFuncAttributeMaxDynamicSharedMemorySize, SMEM_BYTES);
    fused_nms_kernel<<<KCLS, 1024, SMEM_BYTES>>>(boxes, scores, out);
}

// round 7
// speedup vs baseline: 4.7377x; 4.7377x over previous
#include <cuda_runtime.h>
#include <math.h>
#include <stdint.h>

#define R        2048
#define KCLS     20
#define NSC      21
#define IMGW     1333.0f
#define IMGH     800.0f
#define SCORE_TH 0.5f
#define NMS_TH   0.5f
#define TOPK     100
#define KEPT_CAP 192          // TOPK-1 + 64 (last chunk overshoot) max = 163
#define NEG_INF  __int_as_float(0xFF800000)

// ---------------- global scratch (tiny) ----------------
__device__ unsigned long long g_kept[KCLS * TOPK];  // merged keys per class, desc
__device__ int                g_kcnt[KCLS];
__device__ int                g_done = 0;

__device__ __forceinline__ unsigned int fkey(float f) {
    unsigned int u = __float_as_uint(f);
    return (u & 0x80000000u) ? ~u : (u | 0x80000000u);
}
__device__ __forceinline__ float fkey_inv(unsigned int k) {
    unsigned int bits = (k & 0x80000000u) ? (k ^ 0x80000000u) : ~k;
    return __uint_as_float(bits);
}

// ---------------- shared memory layout (dynamic) ----------------
#define OFF_SKEY   0          // u64[2048]   16384
#define OFF_SBOX   16384      // f32[4*2048] 32768
#define OFF_SAREA  49152      // f32[2048]    8192
#define OFF_KEPT   57344      // 5 * f32[192] 3840
#define OFF_FLAGS  61184      // u32[64]       256
#define OFF_DWLO   61440      // u32[64]       256
#define OFF_DWHI   61696      // u32[64]       256
#define OFF_MISC   61952      // snk           16
#define SMEM_BYTES 62080
// merge reuse (CTA 0): sKeys u64[2000]@0, outk u64[100]@16000,
// scnt int[20]@16800, stot@16880

__device__ __forceinline__ float iou_gt(float x1, float y1, float x2, float y2,
                                        float a, float cx1, float cy1,
                                        float cx2, float cy2, float ca) {
    float xx1 = fmaxf(x1, cx1);
    float yy1 = fmaxf(y1, cy1);
    float xx2 = fminf(x2, cx2);
    float yy2 = fminf(y2, cy2);
    float w = fmaxf(xx2 - xx1, 0.0f);
    float h = fmaxf(yy2 - yy1, 0.0f);
    float inter = w * h;
    float uni = a + ca - inter;
    return inter / fmaxf(uni, 1e-9f);
}

__global__ void __launch_bounds__(1024, 1)
fused_nms_kernel(const float* __restrict__ boxes,
                 const float* __restrict__ scores,
                 float* __restrict__ out)
{
    extern __shared__ unsigned char smem[];
    unsigned long long* skey = (unsigned long long*)(smem + OFF_SKEY);
    float* sx1   = (float*)(smem + OFF_SBOX);
    float* sy1   = sx1 + R;
    float* sx2   = sy1 + R;
    float* sy2   = sx2 + R;
    float* sarea = (float*)(smem + OFF_SAREA);
    float* kx1   = (float*)(smem + OFF_KEPT);
    float* ky1   = kx1 + KEPT_CAP;
    float* kx2   = ky1 + KEPT_CAP;
    float* ky2   = kx2 + KEPT_CAP;
    float* karea = ky2 + KEPT_CAP;
    unsigned int* sflags = (unsigned int*)(smem + OFF_FLAGS);
    unsigned int* dwlo   = (unsigned int*)(smem + OFF_DWLO);
    unsigned int* dwhi   = (unsigned int*)(smem + OFF_DWHI);
    int* snk = (int*)(smem + OFF_MISC);

    const int c    = blockIdx.x;
    const int t    = threadIdx.x;
    const int lane = t & 31;
    const int wid  = t >> 5;

    if (t == 0) *snk = 0;

    // ---- phase 1: keys (0 for invalid -> sink in sort) + valid count ----
    bool v01[2];
    #pragma unroll
    for (int e = 0; e < 2; e++) {
        int r = t + e * 1024;
        float4 b4 = ((const float4*)boxes)[r];
        bool fin = isfinite(b4.x) && isfinite(b4.y) &&
                   isfinite(b4.z) && isfinite(b4.w);
        #pragma unroll
        for (int q = 0; q < NSC; q++) fin &= isfinite(scores[r * NSC + q]);
        float s = scores[r * NSC + c];
        bool v = fin && (s > SCORE_TH);
        v01[e] = v;
        skey[r] = v ? (((unsigned long long)fkey(s) << 32) |
                       (unsigned long long)(0xFFFFFFFFu - (unsigned)r))
                    : 0ull;
    }
    const int V = __syncthreads_count(v01[0]) + __syncthreads_count(v01[1]);
    // (counts include their own barriers; skey writes are visible)

    // ---- phase 2: hybrid bitonic sort, descending ----
    for (unsigned int kk = 2; kk <= (unsigned)R; kk <<= 1) {
        unsigned int j = kk >> 1;
        // cross-warp strides via smem
        for (; j >= 32; j >>= 1) {
            #pragma unroll
            for (int e = 0; e < 2; e++) {
                unsigned int i = (unsigned)t + (unsigned)e * 1024u;
                unsigned int ixj = i ^ j;
                if (ixj > i) {
                    unsigned long long a = skey[i], b = skey[ixj];
                    bool descBlock = ((i & kk) == 0);
                    if (descBlock ? (a < b) : (a > b)) { skey[i] = b; skey[ixj] = a; }
                }
            }
            __syncthreads();
        }
        // in-warp strides via shfl (j <= 16)
        {
            unsigned long long v0 = skey[t], v1 = skey[t | 1024];
            bool d0 = (((unsigned)t & kk) == 0);
            bool d1 = ((((unsigned)t | 1024u) & kk) == 0);
            for (; j >= 1; j >>= 1) {
                unsigned long long o0 = __shfl_xor_sync(0xFFFFFFFFu, v0, j);
                unsigned long long o1 = __shfl_xor_sync(0xFFFFFFFFu, v1, j);
                bool up = (((unsigned)t & j) == 0);
                v0 = (d0 == up) ? (v0 > o0 ? v0 : o0) : (v0 < o0 ? v0 : o0);
                v1 = (d1 == up) ? (v1 > o1 ? v1 : o1) : (v1 < o1 ? v1 : o1);
            }
            skey[t] = v0; skey[t | 1024] = v1;
        }
        __syncthreads();
    }

    // ---- phase 3: gather clipped boxes for the valid prefix ----
    #pragma unroll
    for (int e = 0; e < 2; e++) {
        int i = t + e * 1024;
        if (i < V) {
            unsigned long long key = skey[i];
            unsigned int rr = 0xFFFFFFFFu - (unsigned int)(key & 0xFFFFFFFFull);
            float4 b4 = ((const float4*)boxes)[rr];
            float x1 = fminf(fmaxf(b4.x, 0.0f), IMGW);
            float y1 = fminf(fmaxf(b4.y, 0.0f), IMGH);
            float x2 = fminf(fmaxf(b4.z, 0.0f), IMGW);
            float y2 = fminf(fmaxf(b4.w, 0.0f), IMGH);
            sx1[i] = x1; sy1[i] = y1; sx2[i] = x2; sy2[i] = y2;
            sarea[i] = (x2 - x1) * (y2 - y1);
        }
    }
    __syncthreads();

    const int wcap = (V + 63) >> 6;
    int nk = 0;

    // ---- phase 4: chunked on-the-fly NMS, early stop at TOPK kept ----
    for (int ch = 0; ch < wcap && nk < TOPK; ch++) {
        // (a) candidate-vs-kept (64 candidates across 32 warps x 2 halves)
        // (b) 64x64 diagonal IoU ballots — same barrier region
        #pragma unroll
        for (int half = 0; half < 2; half++) {
            int cand = (ch << 6) + wid + (half << 5);
            float x1 = sx1[cand], y1 = sy1[cand];
            float x2 = sx2[cand], y2 = sy2[cand];
            float a = sarea[cand];
            bool loc = false;
            if (cand < V) {
                for (int m = lane; m < nk; m += 32)
                    loc |= (iou_gt(x1, y1, x2, y2, a,
                                   kx1[m], ky1[m], kx2[m], ky2[m], karea[m])
                            > NMS_TH);
            }
            bool sup = __any_sync(0xFFFFFFFFu, loc);
            if (lane == 0) sflags[wid + (half << 5)] = sup ? 1u : 0u;

            int c0 = (ch << 6) + lane;
            int c1 = c0 + 32;
            bool blo = iou_gt(x1, y1, x2, y2, a,
                              sx1[c0], sy1[c0], sx2[c0], sy2[c0], sarea[c0]) > NMS_TH;
            bool bhi = iou_gt(x1, y1, x2, y2, a,
                              sx1[c1], sy1[c1], sx2[c1], sy2[c1], sarea[c1]) > NMS_TH;
            unsigned int rlo = __ballot_sync(0xFFFFFFFFu, blo);
            unsigned int rhi = __ballot_sync(0xFFFFFFFFu, bhi);
            if (lane == 0) {
                dwlo[wid + (half << 5)] = rlo;
                dwhi[wid + (half << 5)] = rhi;
            }
        }
        __syncthreads();

        // (c) warp 0: in-register greedy + append kept
        if (wid == 0) {
            unsigned int f0 = sflags[lane], f1 = sflags[32 + lane];
            unsigned int slo = __ballot_sync(0xFFFFFFFFu, f0 != 0u);
            unsigned int shi = __ballot_sync(0xFFFFFFFFu, f1 != 0u);
            unsigned long long suppressed =
                ((unsigned long long)shi << 32) | (unsigned long long)slo;
            int rem = V - (ch << 6);
            unsigned long long prefix =
                (rem >= 64) ? ~0ull : ((1ull << rem) - 1ull);
            unsigned long long pend = prefix & ~suppressed;

            unsigned long long d0 = (unsigned long long)dwlo[lane] |
                                    ((unsigned long long)dwhi[lane] << 32);
            unsigned long long d1 = (unsigned long long)dwlo[32 + lane] |
                                    ((unsigned long long)dwhi[32 + lane] << 32);
            unsigned long long cur = pend, kept = 0ull;
            while (cur) {
                int b = __ffsll((unsigned long long)cur) - 1;
                kept |= 1ull << b;
                unsigned long long w0 = __shfl_sync(0xFFFFFFFFu, d0, b & 31);
                unsigned long long w1 = __shfl_sync(0xFFFFFFFFu, d1, b & 31);
                unsigned long long dw = (b < 32) ? w0 : w1;
                cur &= ~(1ull << b);
                cur &= ~dw;
            }
            // distribute appends across lanes, ascending bit order
            unsigned long long tk = kept;
            int idx = 0;
            while (tk) {
                int b = __ffsll((unsigned long long)tk) - 1;
                tk &= tk - 1;
                if ((idx & 31) == lane) {
                    int jj = (ch << 6) + b;
                    int pos = nk + idx;
                    kx1[pos] = sx1[jj]; ky1[pos] = sy1[jj];
                    kx2[pos] = sx2[jj]; ky2[pos] = sy2[jj];
                    karea[pos] = sarea[jj];
                    if (pos < TOPK) {
                        unsigned long long key = skey[jj];
                        unsigned int rr = 0xFFFFFFFFu -
                            (unsigned int)(key & 0xFFFFFFFFull);
                        unsigned int flat = (unsigned)c * R + rr;
                        g_kept[c * TOPK + pos] =
                            (key & 0xFFFFFFFF00000000ull) |
                            (unsigned long long)(0xFFFFFFFFu - flat);
                    }
                }
                idx++;
            }
            if (lane == 0) *snk = nk + idx;
        }
        __syncthreads();
        nk = *snk;
    }

    if (t == 0) g_kcnt[c] = (nk > TOPK) ? TOPK : nk;
    __threadfence();
    __syncthreads();
    if (t == 0) atomicAdd(&g_done, 1);

    if (c != 0) return;

    // ================= CTA 0: wait for all classes, then merge =============
    if (t == 0) {
        while (atomicAdd(&g_done, 0) != KCLS) { }
        g_done = 0;                       // reset for next graph replay
        __threadfence();
    }
    __syncthreads();

    unsigned long long* sKeys = (unsigned long long*)(smem + 0);      // [2000]
    unsigned long long* outk  = (unsigned long long*)(smem + 16000);  // [100]
    int* scnt = (int*)(smem + 16800);                                 // [20]
    int* stot = (int*)(smem + 16880);

    if (t < KCLS) scnt[t] = g_kcnt[t];
    __syncthreads();

    for (int e = t; e < KCLS * TOPK; e += 1024) {
        int cc = e / TOPK, p = e % TOPK;
        sKeys[e] = (p < scnt[cc]) ? g_kept[e] : 0ull;
    }
    if (t == 0) {
        int s = 0;
        for (int cc = 0; cc < KCLS; cc++) s += scnt[cc];
        *stot = s;
    }
    __syncthreads();

    // parallel rank selection (no early break -> 19 searches overlap)
    for (int e = t; e < KCLS * TOPK; e += 1024) {
        int cc = e / TOPK, p = e % TOPK;
        if (p >= scnt[cc]) continue;
        unsigned long long key = sKeys[e];
        int rank = p;
        #pragma unroll
        for (int c2 = 0; c2 < KCLS; c2++) {
            if (c2 == cc) continue;
            int lo = 0, hi = scnt[c2];
            while (lo < hi) {
                int mid = (lo + hi) >> 1;
                if (sKeys[c2 * TOPK + mid] > key) lo = mid + 1; else hi = mid;
            }
            rank += lo;
        }
        if (rank < TOPK) outk[rank] = key;
    }
    __syncthreads();

    // degenerate fallback: fewer than TOPK kept -> -inf entries, lowest
    // non-kept flat index first (matches lax.top_k over the masked matrix)
    if (t == 0 && *stot < TOPK) {
        int fill = *stot;
        int flat = 0;
        while (fill < TOPK) {
            int cc = flat >> 11;
            int n = scnt[cc];
            bool is_kept = false;
            for (int q = 0; q < n; q++) {
                unsigned int f2 = 0xFFFFFFFFu -
                    (unsigned int)(sKeys[cc * TOPK + q] & 0xFFFFFFFFull);
                if ((int)f2 == flat) { is_kept = true; break; }
            }
            if (!is_kept) {
                outk[fill] = ((unsigned long long)fkey(NEG_INF) << 32) |
                             (unsigned long long)(0xFFFFFFFFu - (unsigned)flat);
                fill++;
            }
            flat++;
        }
    }
    __syncthreads();

    if (t < TOPK) {
        unsigned long long key = outk[t];
        unsigned int flat = 0xFFFFFFFFu - (unsigned int)(key & 0xFFFFFFFFull);
        float sc = fkey_inv((unsigned int)(key >> 32));
        int cls = (int)(flat >> 11);      // R = 2048 = 2^11
        int rr  = (int)(flat & 2047u);
        float4 b4 = ((const float4*)boxes)[rr];
        out[t] = sc;
        out[TOPK + t * 4 + 0] = fminf(fmaxf(b4.x, 0.0f), IMGW);
        out[TOPK + t * 4 + 1] = fminf(fmaxf(b4.y, 0.0f), IMGH);
        out[TOPK + t * 4 + 2] = fminf(fmaxf(b4.z, 0.0f), IMGW);
        out[TOPK + t * 4 + 3] = fminf(fmaxf(b4.w, 0.0f), IMGH);
        out[TOPK + TOPK * 4 + t]        = (float)cls;
        out[TOPK + TOPK * 4 + TOPK + t] = (float)rr;
    }
}

extern "C" void kernel_launch(void* const* d_in, const int* in_sizes, int n_in,
                              void* d_out, int out_size)
{
    const float* boxes  = (const float*)d_in[0];   // [2048,4]
    const float* scores = (const float*)d_in[1];   // [2048,21]
    float* out = (float*)d_out;

    cudaFuncSetAttribute(fused_nms_kernel,
                         cudaFuncAttributeMaxDynamicSharedMemorySize, SMEM_BYTES);
    fused_nms_kernel<<<KCLS, 1024, SMEM_BYTES>>>(boxes, scores, out);
}

// round 8
// speedup vs baseline: 4.9820x; 1.0515x over previous
#include <cuda_runtime.h>
#include <math.h>
#include <stdint.h>

#define R        2048
#define KCLS     20
#define NSC      21
#define IMGW     1333.0f
#define IMGH     800.0f
#define SCORE_TH 0.5f
#define NMS_TH   0.5f
#define TOPK     100
#define KEPT_CAP 192
#define NEG_INF  __int_as_float(0xFF800000)

// ---------------- global scratch (tiny) ----------------
__device__ unsigned long long g_kept[KCLS * TOPK];  // merged keys per class, desc
__device__ int                g_kcnt[KCLS];
__device__ int                g_done = 0;

__device__ __forceinline__ unsigned int fkey(float f) {
    unsigned int u = __float_as_uint(f);
    return (u & 0x80000000u) ? ~u : (u | 0x80000000u);
}
__device__ __forceinline__ float fkey_inv(unsigned int k) {
    unsigned int bits = (k & 0x80000000u) ? (k ^ 0x80000000u) : ~k;
    return __uint_as_float(bits);
}

// ---------------- shared memory layout (dynamic) ----------------
#define OFF_SKEY   0          // u64[2048]   16384
#define OFF_SBOX   16384      // f32[4*2048] 32768
#define OFF_SAREA  49152      // f32[2048]    8192
#define OFF_KEPT   57344      // 5 * f32[192] 3840
#define OFF_FLAGS  61184      // u32[64]       256
#define OFF_DWLO   61440      // u32[64]       256
#define OFF_DWHI   61696      // u32[64]       256
#define OFF_BAD    61952      // u32[64]       256  (bad-row bitmap)
#define OFF_MISC   62208      // snk, merge flag 16
#define SMEM_BYTES 62224
// merge reuse: sKeys u64[2000]@0, outk u64[100]@16000, scnt@16800, stot@16880

__device__ __forceinline__ float iou_gt(float x1, float y1, float x2, float y2,
                                        float a, float cx1, float cy1,
                                        float cx2, float cy2, float ca) {
    float xx1 = fmaxf(x1, cx1);
    float yy1 = fmaxf(y1, cy1);
    float xx2 = fminf(x2, cx2);
    float yy2 = fminf(y2, cy2);
    float w = fmaxf(xx2 - xx1, 0.0f);
    float h = fmaxf(yy2 - yy1, 0.0f);
    float inter = w * h;
    float uni = a + ca - inter;
    return inter / fmaxf(uni, 1e-9f);
}

__global__ void __launch_bounds__(1024, 1)
fused_nms_kernel(const float* __restrict__ boxes,
                 const float* __restrict__ scores,
                 float* __restrict__ out)
{
    extern __shared__ unsigned char smem[];
    unsigned long long* skey = (unsigned long long*)(smem + OFF_SKEY);
    float* sx1   = (float*)(smem + OFF_SBOX);
    float* sy1   = sx1 + R;
    float* sx2   = sy1 + R;
    float* sy2   = sx2 + R;
    float* sarea = (float*)(smem + OFF_SAREA);
    float* kx1   = (float*)(smem + OFF_KEPT);
    float* ky1   = kx1 + KEPT_CAP;
    float* kx2   = ky1 + KEPT_CAP;
    float* ky2   = kx2 + KEPT_CAP;
    float* karea = ky2 + KEPT_CAP;
    unsigned int* sflags = (unsigned int*)(smem + OFF_FLAGS);
    unsigned int* dwlo   = (unsigned int*)(smem + OFF_DWLO);
    unsigned int* dwhi   = (unsigned int*)(smem + OFF_DWHI);
    unsigned int* sbad   = (unsigned int*)(smem + OFF_BAD);
    int* snk    = (int*)(smem + OFF_MISC);
    int* sMerge = (int*)(smem + OFF_MISC + 4);

    const int c    = blockIdx.x;
    const int t    = threadIdx.x;
    const int lane = t & 31;
    const int wid  = t >> 5;

    if (t == 0) *snk = 0;
    if (t < 64) sbad[t] = 0u;
    __syncthreads();

    // ---- phase 1a: vectorized score-finiteness scan (rare-bad bitmap) ----
    {
        const float4* s4 = (const float4*)scores;
        const int n4 = (R * NSC) / 4;               // 10752
        for (int i = t; i < n4; i += 1024) {
            float4 f = s4[i];
            bool b0 = !isfinite(f.x), b1 = !isfinite(f.y);
            bool b2 = !isfinite(f.z), b3 = !isfinite(f.w);
            if (b0 | b1 | b2 | b3) {
                int e = 4 * i;
                if (b0) { unsigned rr = (unsigned)(e    ) / NSC; atomicOr(&sbad[rr >> 5], 1u << (rr & 31)); }
                if (b1) { unsigned rr = (unsigned)(e + 1) / NSC; atomicOr(&sbad[rr >> 5], 1u << (rr & 31)); }
                if (b2) { unsigned rr = (unsigned)(e + 2) / NSC; atomicOr(&sbad[rr >> 5], 1u << (rr & 31)); }
                if (b3) { unsigned rr = (unsigned)(e + 3) / NSC; atomicOr(&sbad[rr >> 5], 1u << (rr & 31)); }
            }
        }
    }
    __syncthreads();

    // ---- phase 1b: keys (0 for invalid -> sink) + valid count ----
    bool v01[2];
    #pragma unroll
    for (int e = 0; e < 2; e++) {
        int r = t + e * 1024;
        float4 b4 = ((const float4*)boxes)[r];
        bool fin = isfinite(b4.x) && isfinite(b4.y) &&
                   isfinite(b4.z) && isfinite(b4.w);
        fin &= ((sbad[r >> 5] >> (r & 31)) & 1u) == 0u;
        float s = scores[r * NSC + c];
        bool v = fin && (s > SCORE_TH);
        v01[e] = v;
        skey[r] = v ? (((unsigned long long)fkey(s) << 32) |
                       (unsigned long long)(0xFFFFFFFFu - (unsigned)r))
                    : 0ull;
    }
    const int V = __syncthreads_count(v01[0]) + __syncthreads_count(v01[1]);

    // ---- phase 2: hybrid bitonic sort, descending ----
    // stage A: kk = 2..32 entirely in registers (one smem round trip)
    {
        unsigned long long v0 = skey[t], v1 = skey[t | 1024];
        #pragma unroll
        for (unsigned int kk = 2; kk <= 32; kk <<= 1) {
            bool d = ((t & kk) == 0);          // same for t|1024 (kk<=32)
            #pragma unroll
            for (unsigned int j = kk >> 1; j >= 1; j >>= 1) {
                unsigned long long o0 = __shfl_xor_sync(0xFFFFFFFFu, v0, j);
                unsigned long long o1 = __shfl_xor_sync(0xFFFFFFFFu, v1, j);
                bool up = ((t & j) == 0);
                v0 = (d == up) ? (v0 > o0 ? v0 : o0) : (v0 < o0 ? v0 : o0);
                v1 = (d == up) ? (v1 > o1 ? v1 : o1) : (v1 < o1 ? v1 : o1);
            }
        }
        skey[t] = v0; skey[t | 1024] = v1;
    }
    __syncthreads();

    // stage B: kk = 64..2048
    for (unsigned int kk = 64; kk <= (unsigned)R; kk <<= 1) {
        unsigned int j = kk >> 1;
        if (kk == 2048) {
            // j = 1024 in registers: this thread owns both pair elements
            unsigned long long a = skey[t], b = skey[t | 1024];
            // descBlock true for all t<1024 -> descending: high half = max
            skey[t]        = (a > b) ? a : b;
            skey[t | 1024] = (a > b) ? b : a;
            __syncthreads();
            j = 512;
        }
        for (; j >= 32; j >>= 1) {
            #pragma unroll
            for (int e = 0; e < 2; e++) {
                unsigned int i = (unsigned)t + (unsigned)e * 1024u;
                unsigned int ixj = i ^ j;
                if (ixj > i) {
                    unsigned long long a = skey[i], b = skey[ixj];
                    bool descBlock = ((i & kk) == 0);
                    if (descBlock ? (a < b) : (a > b)) { skey[i] = b; skey[ixj] = a; }
                }
            }
            __syncthreads();
        }
        // in-warp strides (j <= 16)
        {
            unsigned long long v0 = skey[t], v1 = skey[t | 1024];
            bool d0 = (((unsigned)t & kk) == 0);
            bool d1 = ((((unsigned)t | 1024u) & kk) == 0);
            #pragma unroll
            for (j = 16; j >= 1; j >>= 1) {
                unsigned long long o0 = __shfl_xor_sync(0xFFFFFFFFu, v0, j);
                unsigned long long o1 = __shfl_xor_sync(0xFFFFFFFFu, v1, j);
                bool up = (((unsigned)t & j) == 0);
                v0 = (d0 == up) ? (v0 > o0 ? v0 : o0) : (v0 < o0 ? v0 : o0);
                v1 = (d1 == up) ? (v1 > o1 ? v1 : o1) : (v1 < o1 ? v1 : o1);
            }
            skey[t] = v0; skey[t | 1024] = v1;
        }
        __syncthreads();
    }

    // ---- phase 3: gather clipped boxes for the valid prefix ----
    #pragma unroll
    for (int e = 0; e < 2; e++) {
        int i = t + e * 1024;
        if (i < V) {
            unsigned long long key = skey[i];
            unsigned int rr = 0xFFFFFFFFu - (unsigned int)(key & 0xFFFFFFFFull);
            float4 b4 = ((const float4*)boxes)[rr];
            float x1 = fminf(fmaxf(b4.x, 0.0f), IMGW);
            float y1 = fminf(fmaxf(b4.y, 0.0f), IMGH);
            float x2 = fminf(fmaxf(b4.z, 0.0f), IMGW);
            float y2 = fminf(fmaxf(b4.w, 0.0f), IMGH);
            sx1[i] = x1; sy1[i] = y1; sx2[i] = x2; sy2[i] = y2;
            sarea[i] = (x2 - x1) * (y2 - y1);
        }
    }
    __syncthreads();

    const int wcap = (V + 63) >> 6;
    int nk = 0;

    // ---- phase 4: chunked on-the-fly NMS, early stop at TOPK kept ----
    for (int ch = 0; ch < wcap && nk < TOPK; ch++) {
        #pragma unroll
        for (int half = 0; half < 2; half++) {
            int cand = (ch << 6) + wid + (half << 5);
            float x1 = sx1[cand], y1 = sy1[cand];
            float x2 = sx2[cand], y2 = sy2[cand];
            float a = sarea[cand];
            bool loc = false;
            if (cand < V) {
                for (int m = lane; m < nk; m += 32)
                    loc |= (iou_gt(x1, y1, x2, y2, a,
                                   kx1[m], ky1[m], kx2[m], ky2[m], karea[m])
                            > NMS_TH);
            }
            bool sup = __any_sync(0xFFFFFFFFu, loc);
            if (lane == 0) sflags[wid + (half << 5)] = sup ? 1u : 0u;

            int c0 = (ch << 6) + lane;
            int c1 = c0 + 32;
            bool blo = iou_gt(x1, y1, x2, y2, a,
                              sx1[c0], sy1[c0], sx2[c0], sy2[c0], sarea[c0]) > NMS_TH;
            bool bhi = iou_gt(x1, y1, x2, y2, a,
                              sx1[c1], sy1[c1], sx2[c1], sy2[c1], sarea[c1]) > NMS_TH;
            unsigned int rlo = __ballot_sync(0xFFFFFFFFu, blo);
            unsigned int rhi = __ballot_sync(0xFFFFFFFFu, bhi);
            if (lane == 0) {
                dwlo[wid + (half << 5)] = rlo;
                dwhi[wid + (half << 5)] = rhi;
            }
        }
        __syncthreads();

        if (wid == 0) {
            unsigned int f0 = sflags[lane], f1 = sflags[32 + lane];
            unsigned int slo = __ballot_sync(0xFFFFFFFFu, f0 != 0u);
            unsigned int shi = __ballot_sync(0xFFFFFFFFu, f1 != 0u);
            unsigned long long suppressed =
                ((unsigned long long)shi << 32) | (unsigned long long)slo;
            int rem = V - (ch << 6);
            unsigned long long prefix =
                (rem >= 64) ? ~0ull : ((1ull << rem) - 1ull);
            unsigned long long pend = prefix & ~suppressed;

            unsigned long long d0 = (unsigned long long)dwlo[lane] |
                                    ((unsigned long long)dwhi[lane] << 32);
            unsigned long long d1 = (unsigned long long)dwlo[32 + lane] |
                                    ((unsigned long long)dwhi[32 + lane] << 32);
            unsigned long long cur = pend, kept = 0ull;
            while (cur) {
                int b = __ffsll((unsigned long long)cur) - 1;
                kept |= 1ull << b;
                unsigned long long w0 = __shfl_sync(0xFFFFFFFFu, d0, b & 31);
                unsigned long long w1 = __shfl_sync(0xFFFFFFFFu, d1, b & 31);
                unsigned long long dw = (b < 32) ? w0 : w1;
                cur &= ~(1ull << b);
                cur &= ~dw;
            }
            unsigned long long tk = kept;
            int idx = 0;
            while (tk) {
                int b = __ffsll((unsigned long long)tk) - 1;
                tk &= tk - 1;
                if ((idx & 31) == lane) {
                    int jj = (ch << 6) + b;
                    int pos = nk + idx;
                    kx1[pos] = sx1[jj]; ky1[pos] = sy1[jj];
                    kx2[pos] = sx2[jj]; ky2[pos] = sy2[jj];
                    karea[pos] = sarea[jj];
                    if (pos < TOPK) {
                        unsigned long long key = skey[jj];
                        unsigned int rr = 0xFFFFFFFFu -
                            (unsigned int)(key & 0xFFFFFFFFull);
                        unsigned int flat = (unsigned)c * R + rr;
                        g_kept[c * TOPK + pos] =
                            (key & 0xFFFFFFFF00000000ull) |
                            (unsigned long long)(0xFFFFFFFFu - flat);
                    }
                }
                idx++;
            }
            if (lane == 0) *snk = nk + idx;
        }
        __syncthreads();
        nk = *snk;
    }

    // ---- completion: last-finishing CTA performs the merge ----
    if (t == 0) {
        g_kcnt[c] = (nk > TOPK) ? TOPK : nk;
        __threadfence();
        int ticket = atomicAdd(&g_done, 1);
        *sMerge = (ticket == KCLS - 1) ? 1 : 0;
        if (*sMerge) g_done = 0;          // reset for next graph replay
    }
    __syncthreads();
    if (*sMerge == 0) return;
    __threadfence();                      // acquire: see all g_kept/g_kcnt

    // ================= merge (single CTA) =================
    unsigned long long* sKeys = (unsigned long long*)(smem + 0);      // [2000]
    unsigned long long* outk  = (unsigned long long*)(smem + 16000);  // [100]
    int* scnt = (int*)(smem + 16800);                                 // [20]
    int* stot = (int*)(smem + 16880);
    __syncthreads();   // everyone past reads of skey region before overwrite

    if (t < KCLS) scnt[t] = g_kcnt[t];
    __syncthreads();

    for (int e = t; e < KCLS * TOPK; e += 1024) {
        int cc = e / TOPK, p = e % TOPK;
        sKeys[e] = (p < scnt[cc]) ? g_kept[e] : 0ull;
    }
    if (t == 0) {
        int s = 0;
        for (int cc = 0; cc < KCLS; cc++) s += scnt[cc];
        *stot = s;
    }
    __syncthreads();

    // parallel rank selection
    for (int e = t; e < KCLS * TOPK; e += 1024) {
        int cc = e / TOPK, p = e % TOPK;
        if (p >= scnt[cc]) continue;
        unsigned long long key = sKeys[e];
        int rank = p;
        #pragma unroll
        for (int c2 = 0; c2 < KCLS; c2++) {
            if (c2 == cc) continue;
            int lo = 0, hi = scnt[c2];
            while (lo < hi) {
                int mid = (lo + hi) >> 1;
                if (sKeys[c2 * TOPK + mid] > key) lo = mid + 1; else hi = mid;
            }
            rank += lo;
        }
        if (rank < TOPK) outk[rank] = key;
    }
    __syncthreads();

    // degenerate fallback: fewer than TOPK kept -> -inf entries, lowest
    // non-kept flat index first (matches lax.top_k over the masked matrix)
    if (t == 0 && *stot < TOPK) {
        int fill = *stot;
        int flat = 0;
        while (fill < TOPK) {
            int cc = flat >> 11;
            int n = scnt[cc];
            bool is_kept = false;
            for (int q = 0; q < n; q++) {
                unsigned int f2 = 0xFFFFFFFFu -
                    (unsigned int)(sKeys[cc * TOPK + q] & 0xFFFFFFFFull);
                if ((int)f2 == flat) { is_kept = true; break; }
            }
            if (!is_kept) {
                outk[fill] = ((unsigned long long)fkey(NEG_INF) << 32) |
                             (unsigned long long)(0xFFFFFFFFu - (unsigned)flat);
                fill++;
            }
            flat++;
        }
    }
    __syncthreads();

    if (t < TOPK) {
        unsigned long long key = outk[t];
        unsigned int flat = 0xFFFFFFFFu - (unsigned int)(key & 0xFFFFFFFFull);
        float sc = fkey_inv((unsigned int)(key >> 32));
        int cls = (int)(flat >> 11);      // R = 2048 = 2^11
        int rr  = (int)(flat & 2047u);
        float4 b4 = ((const float4*)boxes)[rr];
        out[t] = sc;
        out[TOPK + t * 4 + 0] = fminf(fmaxf(b4.x, 0.0f), IMGW);
        out[TOPK + t * 4 + 1] = fminf(fmaxf(b4.y, 0.0f), IMGH);
        out[TOPK + t * 4 + 2] = fminf(fmaxf(b4.z, 0.0f), IMGW);
        out[TOPK + t * 4 + 3] = fminf(fmaxf(b4.w, 0.0f), IMGH);
        out[TOPK + TOPK * 4 + t]        = (float)cls;
        out[TOPK + TOPK * 4 + TOPK + t] = (float)rr;
    }
}

extern "C" void kernel_launch(void* const* d_in, const int* in_sizes, int n_in,
                              void* d_out, int out_size)
{
    const float* boxes  = (const float*)d_in[0];   // [2048,4]
    const float* scores = (const float*)d_in[1];   // [2048,21]
    float* out = (float*)d_out;

    cudaFuncSetAttribute(fused_nms_kernel,
                         cudaFuncAttributeMaxDynamicSharedMemorySize, SMEM_BYTES);
    fused_nms_kernel<<<KCLS, 1024, SMEM_BYTES>>>(boxes, scores, out);
}

// round 9
// speedup vs baseline: 5.4528x; 1.0945x over previous
#include <cuda_runtime.h>
#include <math.h>
#include <stdint.h>

#define R        2048
#define KCLS     20
#define NSC      21
#define IMGW     1333.0f
#define IMGH     800.0f
#define SCORE_TH 0.5f
#define NMS_TH   0.5f
#define TOPK     100
#define KEPT_CAP 192
#define NEG_INF  __int_as_float(0xFF800000)

// ---------------- global scratch (tiny) ----------------
__device__ unsigned long long g_kept[KCLS * TOPK];  // merged keys per class, desc
__device__ int                g_kcnt[KCLS];
__device__ int                g_done = 0;

__device__ __forceinline__ unsigned int fkey(float f) {
    unsigned int u = __float_as_uint(f);
    return (u & 0x80000000u) ? ~u : (u | 0x80000000u);
}
__device__ __forceinline__ float fkey_inv(unsigned int k) {
    unsigned int bits = (k & 0x80000000u) ? (k ^ 0x80000000u) : ~k;
    return __uint_as_float(bits);
}

// ---------------- shared memory layout (dynamic) ----------------
#define OFF_SKEY   0          // u64[2048]   16384
#define OFF_SBOX   16384      // f32[4*2048] 32768
#define OFF_SAREA  49152      // f32[2048]    8192
#define OFF_KEPT   57344      // 5 * f32[192] 3840
#define OFF_FLAGS  61184      // u32[64]       256
#define OFF_DWLO   61440      // u32[64]       256
#define OFF_DWHI   61696      // u32[64]       256
#define OFF_BAD    61952      // u32[64]       256  (bad-row bitmap)
#define OFF_MISC   62208      // snk, merge flag 16
#define SMEM_BYTES 62224
// merge reuse: sKeys u64[2048]@0, outk u64[100]@16384, scnt@17184, stot@17264

__device__ __forceinline__ float iou_gt(float x1, float y1, float x2, float y2,
                                        float a, float cx1, float cy1,
                                        float cx2, float cy2, float ca) {
    float xx1 = fmaxf(x1, cx1);
    float yy1 = fmaxf(y1, cy1);
    float xx2 = fminf(x2, cx2);
    float yy2 = fminf(y2, cy2);
    float w = fmaxf(xx2 - xx1, 0.0f);
    float h = fmaxf(yy2 - yy1, 0.0f);
    float inter = w * h;
    float uni = a + ca - inter;
    return inter / fmaxf(uni, 1e-9f);
}

// 2048-element descending bitonic sort, 1024 threads, hybrid smem/shfl.
__device__ __forceinline__ void bitonic2048_desc(unsigned long long* skey, int t)
{
    // stage A: kk = 2..32 entirely in registers (one smem round trip)
    {
        unsigned long long v0 = skey[t], v1 = skey[t | 1024];
        #pragma unroll
        for (unsigned int kk = 2; kk <= 32; kk <<= 1) {
            bool d = ((t & kk) == 0);          // same for t|1024 (kk<=32)
            #pragma unroll
            for (unsigned int j = kk >> 1; j >= 1; j >>= 1) {
                unsigned long long o0 = __shfl_xor_sync(0xFFFFFFFFu, v0, j);
                unsigned long long o1 = __shfl_xor_sync(0xFFFFFFFFu, v1, j);
                bool up = ((t & j) == 0);
                v0 = (d == up) ? (v0 > o0 ? v0 : o0) : (v0 < o0 ? v0 : o0);
                v1 = (d == up) ? (v1 > o1 ? v1 : o1) : (v1 < o1 ? v1 : o1);
            }
        }
        skey[t] = v0; skey[t | 1024] = v1;
    }
    __syncthreads();

    // stage B: kk = 64..2048
    for (unsigned int kk = 64; kk <= 2048u; kk <<= 1) {
        unsigned int j = kk >> 1;
        if (kk == 2048) {
            // j = 1024 in registers: this thread owns both pair elements
            unsigned long long a = skey[t], b = skey[t | 1024];
            skey[t]        = (a > b) ? a : b;
            skey[t | 1024] = (a > b) ? b : a;
            __syncthreads();
            j = 512;
        }
        for (; j >= 32; j >>= 1) {
            #pragma unroll
            for (int e = 0; e < 2; e++) {
                unsigned int i = (unsigned)t + (unsigned)e * 1024u;
                unsigned int ixj = i ^ j;
                if (ixj > i) {
                    unsigned long long a = skey[i], b = skey[ixj];
                    bool descBlock = ((i & kk) == 0);
                    if (descBlock ? (a < b) : (a > b)) { skey[i] = b; skey[ixj] = a; }
                }
            }
            __syncthreads();
        }
        // in-warp strides (j <= 16)
        {
            unsigned long long v0 = skey[t], v1 = skey[t | 1024];
            bool d0 = (((unsigned)t & kk) == 0);
            bool d1 = ((((unsigned)t | 1024u) & kk) == 0);
            #pragma unroll
            for (j = 16; j >= 1; j >>= 1) {
                unsigned long long o0 = __shfl_xor_sync(0xFFFFFFFFu, v0, j);
                unsigned long long o1 = __shfl_xor_sync(0xFFFFFFFFu, v1, j);
                bool up = (((unsigned)t & j) == 0);
                v0 = (d0 == up) ? (v0 > o0 ? v0 : o0) : (v0 < o0 ? v0 : o0);
                v1 = (d1 == up) ? (v1 > o1 ? v1 : o1) : (v1 < o1 ? v1 : o1);
            }
            skey[t] = v0; skey[t | 1024] = v1;
        }
        __syncthreads();
    }
}

__global__ void __launch_bounds__(1024, 1)
fused_nms_kernel(const float* __restrict__ boxes,
                 const float* __restrict__ scores,
                 float* __restrict__ out)
{
    extern __shared__ unsigned char smem[];
    unsigned long long* skey = (unsigned long long*)(smem + OFF_SKEY);
    float* sx1   = (float*)(smem + OFF_SBOX);
    float* sy1   = sx1 + R;
    float* sx2   = sy1 + R;
    float* sy2   = sx2 + R;
    float* sarea = (float*)(smem + OFF_SAREA);
    float* kx1   = (float*)(smem + OFF_KEPT);
    float* ky1   = kx1 + KEPT_CAP;
    float* kx2   = ky1 + KEPT_CAP;
    float* ky2   = kx2 + KEPT_CAP;
    float* karea = ky2 + KEPT_CAP;
    unsigned int* sflags = (unsigned int*)(smem + OFF_FLAGS);
    unsigned int* dwlo   = (unsigned int*)(smem + OFF_DWLO);
    unsigned int* dwhi   = (unsigned int*)(smem + OFF_DWHI);
    unsigned int* sbad   = (unsigned int*)(smem + OFF_BAD);
    int* snk    = (int*)(smem + OFF_MISC);
    int* sMerge = (int*)(smem + OFF_MISC + 4);

    const int c    = blockIdx.x;
    const int t    = threadIdx.x;
    const int lane = t & 31;
    const int wid  = t >> 5;

    if (t == 0) *snk = 0;
    if (t < 64) sbad[t] = 0u;
    __syncthreads();

    // ---- phase 1a: vectorized score-finiteness scan (rare-bad bitmap) ----
    {
        const float4* s4 = (const float4*)scores;
        const int n4 = (R * NSC) / 4;               // 10752
        for (int i = t; i < n4; i += 1024) {
            float4 f = s4[i];
            bool b0 = !isfinite(f.x), b1 = !isfinite(f.y);
            bool b2 = !isfinite(f.z), b3 = !isfinite(f.w);
            if (b0 | b1 | b2 | b3) {
                int e = 4 * i;
                if (b0) { unsigned rr = (unsigned)(e    ) / NSC; atomicOr(&sbad[rr >> 5], 1u << (rr & 31)); }
                if (b1) { unsigned rr = (unsigned)(e + 1) / NSC; atomicOr(&sbad[rr >> 5], 1u << (rr & 31)); }
                if (b2) { unsigned rr = (unsigned)(e + 2) / NSC; atomicOr(&sbad[rr >> 5], 1u << (rr & 31)); }
                if (b3) { unsigned rr = (unsigned)(e + 3) / NSC; atomicOr(&sbad[rr >> 5], 1u << (rr & 31)); }
            }
        }
    }
    __syncthreads();

    // ---- phase 1b: keys (0 for invalid -> sink) + valid count ----
    bool v01[2];
    #pragma unroll
    for (int e = 0; e < 2; e++) {
        int r = t + e * 1024;
        float4 b4 = ((const float4*)boxes)[r];
        bool fin = isfinite(b4.x) && isfinite(b4.y) &&
                   isfinite(b4.z) && isfinite(b4.w);
        fin &= ((sbad[r >> 5] >> (r & 31)) & 1u) == 0u;
        float s = scores[r * NSC + c];
        bool v = fin && (s > SCORE_TH);
        v01[e] = v;
        skey[r] = v ? (((unsigned long long)fkey(s) << 32) |
                       (unsigned long long)(0xFFFFFFFFu - (unsigned)r))
                    : 0ull;
    }
    const int V = __syncthreads_count(v01[0]) + __syncthreads_count(v01[1]);

    // ---- phase 2: sort keys descending ----
    bitonic2048_desc(skey, t);

    // ---- phase 3: gather clipped boxes for the valid prefix ----
    #pragma unroll
    for (int e = 0; e < 2; e++) {
        int i = t + e * 1024;
        if (i < V) {
            unsigned long long key = skey[i];
            unsigned int rr = 0xFFFFFFFFu - (unsigned int)(key & 0xFFFFFFFFull);
            float4 b4 = ((const float4*)boxes)[rr];
            float x1 = fminf(fmaxf(b4.x, 0.0f), IMGW);
            float y1 = fminf(fmaxf(b4.y, 0.0f), IMGH);
            float x2 = fminf(fmaxf(b4.z, 0.0f), IMGW);
            float y2 = fminf(fmaxf(b4.w, 0.0f), IMGH);
            sx1[i] = x1; sy1[i] = y1; sx2[i] = x2; sy2[i] = y2;
            sarea[i] = (x2 - x1) * (y2 - y1);
        }
    }
    __syncthreads();

    const int wcap = (V + 63) >> 6;
    int nk = 0;

    // ---- phase 4: chunked on-the-fly NMS, early stop at TOPK kept ----
    for (int ch = 0; ch < wcap && nk < TOPK; ch++) {
        #pragma unroll
        for (int half = 0; half < 2; half++) {
            int cand = (ch << 6) + wid + (half << 5);
            float x1 = sx1[cand], y1 = sy1[cand];
            float x2 = sx2[cand], y2 = sy2[cand];
            float a = sarea[cand];
            bool loc = false;
            if (cand < V) {
                for (int m = lane; m < nk; m += 32)
                    loc |= (iou_gt(x1, y1, x2, y2, a,
                                   kx1[m], ky1[m], kx2[m], ky2[m], karea[m])
                            > NMS_TH);
            }
            bool sup = __any_sync(0xFFFFFFFFu, loc);
            if (lane == 0) sflags[wid + (half << 5)] = sup ? 1u : 0u;

            int c0 = (ch << 6) + lane;
            int c1 = c0 + 32;
            bool blo = iou_gt(x1, y1, x2, y2, a,
                              sx1[c0], sy1[c0], sx2[c0], sy2[c0], sarea[c0]) > NMS_TH;
            bool bhi = iou_gt(x1, y1, x2, y2, a,
                              sx1[c1], sy1[c1], sx2[c1], sy2[c1], sarea[c1]) > NMS_TH;
            unsigned int rlo = __ballot_sync(0xFFFFFFFFu, blo);
            unsigned int rhi = __ballot_sync(0xFFFFFFFFu, bhi);
            if (lane == 0) {
                dwlo[wid + (half << 5)] = rlo;
                dwhi[wid + (half << 5)] = rhi;
            }
        }
        __syncthreads();

        if (wid == 0) {
            unsigned int f0 = sflags[lane], f1 = sflags[32 + lane];
            unsigned int slo = __ballot_sync(0xFFFFFFFFu, f0 != 0u);
            unsigned int shi = __ballot_sync(0xFFFFFFFFu, f1 != 0u);
            unsigned long long suppressed =
                ((unsigned long long)shi << 32) | (unsigned long long)slo;
            int rem = V - (ch << 6);
            unsigned long long prefix =
                (rem >= 64) ? ~0ull : ((1ull << rem) - 1ull);
            unsigned long long pend = prefix & ~suppressed;

            unsigned long long d0 = (unsigned long long)dwlo[lane] |
                                    ((unsigned long long)dwhi[lane] << 32);
            unsigned long long d1 = (unsigned long long)dwlo[32 + lane] |
                                    ((unsigned long long)dwhi[32 + lane] << 32);
            unsigned long long cur = pend, kept = 0ull;
            while (cur) {
                int b = __ffsll((unsigned long long)cur) - 1;
                kept |= 1ull << b;
                unsigned long long w0 = __shfl_sync(0xFFFFFFFFu, d0, b & 31);
                unsigned long long w1 = __shfl_sync(0xFFFFFFFFu, d1, b & 31);
                unsigned long long dw = (b < 32) ? w0 : w1;
                cur &= ~(1ull << b);
                cur &= ~dw;
            }
            unsigned long long tk = kept;
            int idx = 0;
            while (tk) {
                int b = __ffsll((unsigned long long)tk) - 1;
                tk &= tk - 1;
                if ((idx & 31) == lane) {
                    int jj = (ch << 6) + b;
                    int pos = nk + idx;
                    kx1[pos] = sx1[jj]; ky1[pos] = sy1[jj];
                    kx2[pos] = sx2[jj]; ky2[pos] = sy2[jj];
                    karea[pos] = sarea[jj];
                    if (pos < TOPK) {
                        unsigned long long key = skey[jj];
                        unsigned int rr = 0xFFFFFFFFu -
                            (unsigned int)(key & 0xFFFFFFFFull);
                        unsigned int flat = (unsigned)c * R + rr;
                        g_kept[c * TOPK + pos] =
                            (key & 0xFFFFFFFF00000000ull) |
                            (unsigned long long)(0xFFFFFFFFu - flat);
                    }
                }
                idx++;
            }
            if (lane == 0) *snk = nk + idx;
        }
        __syncthreads();
        nk = *snk;
    }

    // ---- completion: last-finishing CTA performs the merge ----
    if (t == 0) {
        g_kcnt[c] = (nk > TOPK) ? TOPK : nk;
        __threadfence();
        int ticket = atomicAdd(&g_done, 1);
        *sMerge = (ticket == KCLS - 1) ? 1 : 0;
        if (*sMerge) g_done = 0;          // reset for next graph replay
    }
    __syncthreads();
    if (*sMerge == 0) return;
    __threadfence();                      // acquire: see all g_kept/g_kcnt

    // ================= merge (single CTA): sort 2048 padded keys ===========
    unsigned long long* sKeys = (unsigned long long*)(smem + 0);      // [2048]
    unsigned long long* outk  = (unsigned long long*)(smem + 16384);  // [100]
    int* scnt = (int*)(smem + 17184);                                 // [20]
    int* stot = (int*)(smem + 17264);
    __syncthreads();   // all threads past skey-region reads before overwrite

    if (t < KCLS) scnt[t] = g_kcnt[t];
    __syncthreads();

    #pragma unroll
    for (int e = 0; e < 2; e++) {
        int i = t + e * 1024;
        unsigned long long mk = 0ull;
        if (i < KCLS * TOPK) {
            int cc = i / TOPK, p = i % TOPK;
            if (p < scnt[cc]) mk = g_kept[i];
        }
        sKeys[i] = mk;
    }
    if (t == 0) {
        int s = 0;
        for (int cc = 0; cc < KCLS; cc++) s += scnt[cc];
        *stot = s;
    }
    __syncthreads();

    bitonic2048_desc(sKeys, t);

    if (t < TOPK) outk[t] = sKeys[t];
    __syncthreads();

    // degenerate fallback: fewer than TOPK kept -> -inf entries, lowest
    // non-kept flat index first (reads g_kept per-class layout from global)
    if (t == 0 && *stot < TOPK) {
        int fill = *stot;
        int flat = 0;
        while (fill < TOPK) {
            int cc = flat >> 11;
            int n = scnt[cc];
            bool is_kept = false;
            for (int q = 0; q < n; q++) {
                unsigned int f2 = 0xFFFFFFFFu -
                    (unsigned int)(g_kept[cc * TOPK + q] & 0xFFFFFFFFull);
                if ((int)f2 == flat) { is_kept = true; break; }
            }
            if (!is_kept) {
                outk[fill] = ((unsigned long long)fkey(NEG_INF) << 32) |
                             (unsigned long long)(0xFFFFFFFFu - (unsigned)flat);
                fill++;
            }
            flat++;
        }
    }
    __syncthreads();

    if (t < TOPK) {
        unsigned long long key = outk[t];
        unsigned int flat = 0xFFFFFFFFu - (unsigned int)(key & 0xFFFFFFFFull);
        float sc = fkey_inv((unsigned int)(key >> 32));
        int cls = (int)(flat >> 11);      // R = 2048 = 2^11
        int rr  = (int)(flat & 2047u);
        float4 b4 = ((const float4*)boxes)[rr];
        out[t] = sc;
        out[TOPK + t * 4 + 0] = fminf(fmaxf(b4.x, 0.0f), IMGW);
        out[TOPK + t * 4 + 1] = fminf(fmaxf(b4.y, 0.0f), IMGH);
        out[TOPK + t * 4 + 2] = fminf(fmaxf(b4.z, 0.0f), IMGW);
        out[TOPK + t * 4 + 3] = fminf(fmaxf(b4.w, 0.0f), IMGH);
        out[TOPK + TOPK * 4 + t]        = (float)cls;
        out[TOPK + TOPK * 4 + TOPK + t] = (float)rr;
    }
}

extern "C" void kernel_launch(void* const* d_in, const int* in_sizes, int n_in,
                              void* d_out, int out_size)
{
    const float* boxes  = (const float*)d_in[0];   // [2048,4]
    const float* scores = (const float*)d_in[1];   // [2048,21]
    float* out = (float*)d_out;

    cudaFuncSetAttribute(fused_nms_kernel,
                         cudaFuncAttributeMaxDynamicSharedMemorySize, SMEM_BYTES);
    fused_nms_kernel<<<KCLS, 1024, SMEM_BYTES>>>(boxes, scores, out);
}

// round 10
// speedup vs baseline: 7.1416x; 1.3097x over previous
#include <cuda_runtime.h>
#include <math.h>
#include <stdint.h>

#define R        2048
#define KCLS     20
#define NSC      21
#define IMGW     1333.0f
#define IMGH     800.0f
#define SCORE_TH 0.5f
#define NMS_TH   0.5f
#define TOPK     100
#define KEPT_CAP 192
#define NEG_INF  __int_as_float(0xFF800000)

// ---------------- global scratch (tiny) ----------------
__device__ unsigned long long g_kept[KCLS * TOPK];  // merged keys per class, desc
__device__ int                g_kcnt[KCLS];
__device__ int                g_done = 0;

__device__ __forceinline__ unsigned int fkey(float f) {
    unsigned int u = __float_as_uint(f);
    return (u & 0x80000000u) ? ~u : (u | 0x80000000u);
}
__device__ __forceinline__ float fkey_inv(unsigned int k) {
    unsigned int bits = (k & 0x80000000u) ? (k ^ 0x80000000u) : ~k;
    return __uint_as_float(bits);
}

// ---------------- shared memory layout (dynamic) ----------------
#define OFF_SKEY   0          // u64[2048]   16384
#define OFF_SBOX   16384      // f32[4*2048] 32768
#define OFF_SAREA  49152      // f32[2048]    8192
#define OFF_KEPT   57344      // 5 * f32[192] 3840
#define OFF_FLAGS  61184      // u32[64]       256
#define OFF_DWLO   61440      // u32[64]       256  (also hist scratch)
#define OFF_DWHI   61696      // u32[64]       256
#define OFF_BAD    61952      // u32[64]       256
#define OFF_MISC   62208      // snk,sMerge,sB,sS,sCnt  32
#define OFF_BINS   62240      // u32[1024]    4096
#define OFF_CAND   66336      // u64[512]     4096
#define SMEM_BYTES 70432
// merge reuse: sKeys u64[2048]@0, outk u64[100]@16384, scnt int[20]@17184

__device__ __forceinline__ float iou_gt(float x1, float y1, float x2, float y2,
                                        float a, float cx1, float cy1,
                                        float cx2, float cy2, float ca) {
    float xx1 = fmaxf(x1, cx1);
    float yy1 = fmaxf(y1, cy1);
    float xx2 = fminf(x2, cx2);
    float yy2 = fminf(y2, cy2);
    float w = fmaxf(xx2 - xx1, 0.0f);
    float h = fmaxf(yy2 - yy1, 0.0f);
    float inter = w * h;
    float uni = a + ca - inter;
    return inter / fmaxf(uni, 1e-9f);
}

// N-element descending bitonic sort (N in {128,256,512,1024,2048}).
// Threads t < N/2 are active; all 1024 threads must call (block barriers).
template<int N>
__device__ __forceinline__ void bitonicN_desc(unsigned long long* a, int t)
{
    const int H = N >> 1;
    const bool act = (t < H);
    // stage A: kk = 2..32 in registers (shfl); element indices t and t|H share low bits
    if (act) {
        unsigned long long v0 = a[t], v1 = a[t | H];
        #pragma unroll
        for (unsigned int kk = 2; kk <= 32; kk <<= 1) {
            bool d = ((t & kk) == 0);
            #pragma unroll
            for (unsigned int j = kk >> 1; j >= 1; j >>= 1) {
                unsigned long long o0 = __shfl_xor_sync(0xFFFFFFFFu, v0, j);
                unsigned long long o1 = __shfl_xor_sync(0xFFFFFFFFu, v1, j);
                bool up = ((t & j) == 0);
                v0 = (d == up) ? (v0 > o0 ? v0 : o0) : (v0 < o0 ? v0 : o0);
                v1 = (d == up) ? (v1 > o1 ? v1 : o1) : (v1 < o1 ? v1 : o1);
            }
        }
        a[t] = v0; a[t | H] = v1;
    }
    __syncthreads();

    for (unsigned int kk = 64; kk <= (unsigned int)N; kk <<= 1) {
        unsigned int j = kk >> 1;
        if (kk == (unsigned int)N) {
            if (act) {
                unsigned long long x = a[t], y = a[t | H];
                a[t]     = (x > y) ? x : y;
                a[t | H] = (x > y) ? y : x;
            }
            __syncthreads();
            j = (unsigned int)(H >> 1);
        }
        for (; j >= 32; j >>= 1) {
            if (act) {
                #pragma unroll
                for (int e = 0; e < 2; e++) {
                    unsigned int i = (unsigned int)t + (unsigned int)(e * H);
                    unsigned int ixj = i ^ j;
                    if (ixj > i) {
                        unsigned long long x = a[i], y = a[ixj];
                        bool descBlock = ((i & kk) == 0);
                        if (descBlock ? (x < y) : (x > y)) { a[i] = y; a[ixj] = x; }
                    }
                }
            }
            __syncthreads();
        }
        if (act) {
            unsigned long long v0 = a[t], v1 = a[t | H];
            bool d0 = (((unsigned)t & kk) == 0);
            bool d1 = ((((unsigned)t | (unsigned)H) & kk) == 0);
            #pragma unroll
            for (unsigned int jj = 16; jj >= 1; jj >>= 1) {
                unsigned long long o0 = __shfl_xor_sync(0xFFFFFFFFu, v0, jj);
                unsigned long long o1 = __shfl_xor_sync(0xFFFFFFFFu, v1, jj);
                bool up = (((unsigned)t & jj) == 0);
                v0 = (d0 == up) ? (v0 > o0 ? v0 : o0) : (v0 < o0 ? v0 : o0);
                v1 = (d1 == up) ? (v1 > o1 ? v1 : o1) : (v1 < o1 ? v1 : o1);
            }
            a[t] = v0; a[t | H] = v1;
        }
        __syncthreads();
    }
}

// Given bins[1024], find largest bin B with suffix-count >= target.
// Writes *sB, *sS (survivor count) from the unique boundary thread.
__device__ __forceinline__ void hist_select(const unsigned int* bins,
                                            unsigned int* scratch, int t,
                                            int target, int* sB, int* sS)
{
    const int lane = t & 31, w = t >> 5;
    unsigned int v = bins[t];
    #pragma unroll
    for (int d = 1; d < 32; d <<= 1) {
        unsigned int o = __shfl_down_sync(0xFFFFFFFFu, v, d);
        if (lane + d < 32) v += o;
    }
    if (lane == 0) scratch[w] = v;
    __syncthreads();
    if (t < 32) {
        unsigned int wv = scratch[t];
        #pragma unroll
        for (int d = 1; d < 32; d <<= 1) {
            unsigned int o = __shfl_down_sync(0xFFFFFFFFu, wv, d);
            if (t + d < 32) wv += o;
        }
        scratch[32 + t] = wv;
    }
    __syncthreads();
    unsigned int suf  = v + ((w < 31) ? scratch[32 + w + 1] : 0u);
    unsigned int sufn = suf - bins[t];
    if ((int)suf >= target && (int)sufn < target) { *sB = t; *sS = (int)suf; }
    __syncthreads();
}

__global__ void __launch_bounds__(1024, 1)
fused_nms_kernel(const float* __restrict__ boxes,
                 const float* __restrict__ scores,
                 float* __restrict__ out)
{
    extern __shared__ unsigned char smem[];
    unsigned long long* skey = (unsigned long long*)(smem + OFF_SKEY);
    float* sx1   = (float*)(smem + OFF_SBOX);
    float* sy1   = sx1 + R;
    float* sx2   = sy1 + R;
    float* sy2   = sx2 + R;
    float* sarea = (float*)(smem + OFF_SAREA);
    float* kx1   = (float*)(smem + OFF_KEPT);
    float* ky1   = kx1 + KEPT_CAP;
    float* kx2   = ky1 + KEPT_CAP;
    float* ky2   = kx2 + KEPT_CAP;
    float* karea = ky2 + KEPT_CAP;
    unsigned int* sflags  = (unsigned int*)(smem + OFF_FLAGS);
    unsigned int* dwlo    = (unsigned int*)(smem + OFF_DWLO);
    unsigned int* dwhi    = (unsigned int*)(smem + OFF_DWHI);
    unsigned int* sbad    = (unsigned int*)(smem + OFF_BAD);
    unsigned int* bins    = (unsigned int*)(smem + OFF_BINS);
    unsigned long long* cand = (unsigned long long*)(smem + OFF_CAND);
    int* snk    = (int*)(smem + OFF_MISC);
    int* sMerge = (int*)(smem + OFF_MISC + 4);
    int* sB     = (int*)(smem + OFF_MISC + 8);
    int* sS     = (int*)(smem + OFF_MISC + 12);
    int* sCnt   = (int*)(smem + OFF_MISC + 16);

    const int c    = blockIdx.x;
    const int t    = threadIdx.x;
    const int lane = t & 31;
    const int wid  = t >> 5;

    if (t < 64) sbad[t] = 0u;
    __syncthreads();

    // ---- phase 1a: vectorized score-finiteness scan (rare-bad bitmap) ----
    {
        const float4* s4 = (const float4*)scores;
        const int n4 = (R * NSC) / 4;
        for (int i = t; i < n4; i += 1024) {
            float4 f = s4[i];
            bool b0 = !isfinite(f.x), b1 = !isfinite(f.y);
            bool b2 = !isfinite(f.z), b3 = !isfinite(f.w);
            if (b0 | b1 | b2 | b3) {
                int e = 4 * i;
                if (b0) { unsigned rr = (unsigned)(e    ) / NSC; atomicOr(&sbad[rr >> 5], 1u << (rr & 31)); }
                if (b1) { unsigned rr = (unsigned)(e + 1) / NSC; atomicOr(&sbad[rr >> 5], 1u << (rr & 31)); }
                if (b2) { unsigned rr = (unsigned)(e + 2) / NSC; atomicOr(&sbad[rr >> 5], 1u << (rr & 31)); }
                if (b3) { unsigned rr = (unsigned)(e + 3) / NSC; atomicOr(&sbad[rr >> 5], 1u << (rr & 31)); }
            }
        }
    }
    __syncthreads();

    // ---- phase 1b: keys (0 for invalid -> sink) + valid count ----
    unsigned long long key0, key1;
    bool v0f, v1f;
    {
        int r0 = t;
        float4 b4 = ((const float4*)boxes)[r0];
        bool fin = isfinite(b4.x) && isfinite(b4.y) && isfinite(b4.z) && isfinite(b4.w);
        fin &= ((sbad[r0 >> 5] >> (r0 & 31)) & 1u) == 0u;
        float s = scores[r0 * NSC + c];
        v0f = fin && (s > SCORE_TH);
        key0 = v0f ? (((unsigned long long)fkey(s) << 32) |
                      (unsigned long long)(0xFFFFFFFFu - (unsigned)r0)) : 0ull;
        skey[r0] = key0;
        int r1 = t + 1024;
        float4 c4 = ((const float4*)boxes)[r1];
        bool fin1 = isfinite(c4.x) && isfinite(c4.y) && isfinite(c4.z) && isfinite(c4.w);
        fin1 &= ((sbad[r1 >> 5] >> (r1 & 31)) & 1u) == 0u;
        float s1 = scores[r1 * NSC + c];
        v1f = fin1 && (s1 > SCORE_TH);
        key1 = v1f ? (((unsigned long long)fkey(s1) << 32) |
                      (unsigned long long)(0xFFFFFFFFu - (unsigned)r1)) : 0ull;
        skey[r1] = key1;
    }
    const int V = __syncthreads_count(v0f) + __syncthreads_count(v1f);

    // ---- phase 2: exact top-S selection (monotone-bin histogram) ----
    // Valid scores in [0.5,1) have key>>55 == 0x17E, making bits[54:45] a
    // monotone bin index. Verified by ballot; any violation -> full sort.
    bool okb = (key0 == 0ull || (key0 >> 55) == 0x17Eull) &&
               (key1 == 0ull || (key1 >> 55) == 0x17Eull);
    int nok = __syncthreads_count(okb);
    bool selOK = (nok == 1024) && (V > 0);
    int S = 0, B = 1024;
    if (selOK) {
        bins[t] = 0u;
        if (t == 0) { *sB = 1024; *sS = 0; *sCnt = 0; }
        __syncthreads();
        if (key0) atomicAdd(&bins[(unsigned)((key0 >> 45) & 1023)], 1u);
        if (key1) atomicAdd(&bins[(unsigned)((key1 >> 45) & 1023)], 1u);
        __syncthreads();
        int target = (V < 256) ? V : 256;
        hist_select(bins, dwlo, t, target, sB, sS);
        S = *sS; B = *sB;
        if (S > 0 && S <= 512) {
            if (t < 512) cand[t] = 0ull;
            __syncthreads();
            if (key0 && (int)((key0 >> 45) & 1023) >= B) cand[atomicAdd(sCnt, 1)] = key0;
            if (key1 && (int)((key1 >> 45) & 1023) >= B) cand[atomicAdd(sCnt, 1)] = key1;
            __syncthreads();
            if (S <= 128)      bitonicN_desc<128>(cand, t);
            else if (S <= 256) bitonicN_desc<256>(cand, t);
            else               bitonicN_desc<512>(cand, t);
        } else {
            selOK = false;
        }
    }

    // ---- phases 3+4: gather + chunked NMS (retry with full sort if needed) ----
    int nk = 0;
    for (int attempt = 0; attempt < 2; attempt++) {
        const bool useSel = (attempt == 0) && selOK;
        const unsigned long long* ckey;
        int CV;
        if (useSel) { ckey = cand; CV = S; }
        else { bitonicN_desc<2048>(skey, t); ckey = skey; CV = V; }

        for (int i = t; i < CV; i += 1024) {
            unsigned long long key = ckey[i];
            unsigned int rr = 0xFFFFFFFFu - (unsigned int)(key & 0xFFFFFFFFull);
            float4 b4 = ((const float4*)boxes)[rr];
            float x1 = fminf(fmaxf(b4.x, 0.0f), IMGW);
            float y1 = fminf(fmaxf(b4.y, 0.0f), IMGH);
            float x2 = fminf(fmaxf(b4.z, 0.0f), IMGW);
            float y2 = fminf(fmaxf(b4.w, 0.0f), IMGH);
            sx1[i] = x1; sy1[i] = y1; sx2[i] = x2; sy2[i] = y2;
            sarea[i] = (x2 - x1) * (y2 - y1);
        }
        if (t == 0) *snk = 0;
        __syncthreads();
        nk = 0;

        const int wcap = (CV + 63) >> 6;
        for (int ch = 0; ch < wcap && nk < TOPK; ch++) {
            #pragma unroll
            for (int half = 0; half < 2; half++) {
                int cd = (ch << 6) + wid + (half << 5);
                float x1 = sx1[cd], y1 = sy1[cd];
                float x2 = sx2[cd], y2 = sy2[cd];
                float a = sarea[cd];
                bool loc = false;
                if (cd < CV) {
                    for (int m = lane; m < nk; m += 32)
                        loc |= (iou_gt(x1, y1, x2, y2, a,
                                       kx1[m], ky1[m], kx2[m], ky2[m], karea[m])
                                > NMS_TH);
                }
                bool sup = __any_sync(0xFFFFFFFFu, loc);
                if (lane == 0) sflags[wid + (half << 5)] = sup ? 1u : 0u;

                int c0 = (ch << 6) + lane;
                int c1 = c0 + 32;
                bool blo = iou_gt(x1, y1, x2, y2, a,
                                  sx1[c0], sy1[c0], sx2[c0], sy2[c0], sarea[c0]) > NMS_TH;
                bool bhi = iou_gt(x1, y1, x2, y2, a,
                                  sx1[c1], sy1[c1], sx2[c1], sy2[c1], sarea[c1]) > NMS_TH;
                unsigned int rlo = __ballot_sync(0xFFFFFFFFu, blo);
                unsigned int rhi = __ballot_sync(0xFFFFFFFFu, bhi);
                if (lane == 0) {
                    dwlo[wid + (half << 5)] = rlo;
                    dwhi[wid + (half << 5)] = rhi;
                }
            }
            __syncthreads();

            if (wid == 0) {
                unsigned int f0 = sflags[lane], f1 = sflags[32 + lane];
                unsigned int slo = __ballot_sync(0xFFFFFFFFu, f0 != 0u);
                unsigned int shi = __ballot_sync(0xFFFFFFFFu, f1 != 0u);
                unsigned long long suppressed =
                    ((unsigned long long)shi << 32) | (unsigned long long)slo;
                int rem = CV - (ch << 6);
                unsigned long long prefix =
                    (rem >= 64) ? ~0ull : ((1ull << rem) - 1ull);
                unsigned long long pend = prefix & ~suppressed;

                unsigned long long d0 = (unsigned long long)dwlo[lane] |
                                        ((unsigned long long)dwhi[lane] << 32);
                unsigned long long d1 = (unsigned long long)dwlo[32 + lane] |
                                        ((unsigned long long)dwhi[32 + lane] << 32);
                unsigned long long cur = pend, kept = 0ull;
                while (cur) {
                    int b = __ffsll((unsigned long long)cur) - 1;
                    kept |= 1ull << b;
                    unsigned long long w0 = __shfl_sync(0xFFFFFFFFu, d0, b & 31);
                    unsigned long long w1 = __shfl_sync(0xFFFFFFFFu, d1, b & 31);
                    unsigned long long dw = (b < 32) ? w0 : w1;
                    cur &= ~(1ull << b);
                    cur &= ~dw;
                }
                unsigned long long tk = kept;
                int idx = 0;
                while (tk) {
                    int b = __ffsll((unsigned long long)tk) - 1;
                    tk &= tk - 1;
                    if ((idx & 31) == lane) {
                        int jj = (ch << 6) + b;
                        int pos = nk + idx;
                        kx1[pos] = sx1[jj]; ky1[pos] = sy1[jj];
                        kx2[pos] = sx2[jj]; ky2[pos] = sy2[jj];
                        karea[pos] = sarea[jj];
                        if (pos < TOPK) {
                            unsigned long long key = ckey[jj];
                            unsigned int rr = 0xFFFFFFFFu -
                                (unsigned int)(key & 0xFFFFFFFFull);
                            unsigned int flat = (unsigned)c * R + rr;
                            g_kept[c * TOPK + pos] =
                                (key & 0xFFFFFFFF00000000ull) |
                                (unsigned long long)(0xFFFFFFFFu - flat);
                        }
                    }
                    idx++;
                }
                if (lane == 0) *snk = nk + idx;
            }
            __syncthreads();
            nk = *snk;
        }
        if (nk >= TOPK || CV >= V || !useSel) break;
    }

    // ---- completion: last-finishing CTA performs the merge ----
    if (t == 0) {
        g_kcnt[c] = (nk > TOPK) ? TOPK : nk;
        __threadfence();
        int ticket = atomicAdd(&g_done, 1);
        *sMerge = (ticket == KCLS - 1) ? 1 : 0;
        if (*sMerge) g_done = 0;          // reset for next graph replay
    }
    __syncthreads();
    if (*sMerge == 0) return;
    __threadfence();                      // acquire: see all g_kept/g_kcnt

    // ================= merge (single CTA) =================
    unsigned long long* sKeys = (unsigned long long*)(smem + 0);      // [2048]
    unsigned long long* outk  = (unsigned long long*)(smem + 16384);  // [100]
    int* scnt = (int*)(smem + 17184);                                 // [20]
    __syncthreads();   // all threads past skey-region reads before overwrite

    if (t < KCLS) scnt[t] = g_kcnt[t];
    __syncthreads();

    unsigned long long k0 = 0ull, k1 = 0ull;
    bool q0 = false, q1 = false;
    {
        int i0 = t;
        if (i0 < KCLS * TOPK) {
            int cc = i0 / TOPK, p = i0 % TOPK;
            if (p < scnt[cc]) { k0 = g_kept[i0]; q0 = true; }
        }
        int i1 = t + 1024;
        if (i1 < KCLS * TOPK) {
            int cc = i1 / TOPK, p = i1 % TOPK;
            if (p < scnt[cc]) { k1 = g_kept[i1]; q1 = true; }
        }
    }
    const int stotv = __syncthreads_count(q0) + __syncthreads_count(q1);
    bool mok = (!q0 || (k0 >> 55) == 0x17Eull) &&
               (!q1 || (k1 >> 55) == 0x17Eull);
    int mnok = __syncthreads_count(mok);
    bool mSel = (mnok == 1024) && (stotv > 0);
    if (mSel) {
        bins[t] = 0u;
        if (t == 0) { *sB = 1024; *sS = 0; *sCnt = 0; }
        __syncthreads();
        if (q0) atomicAdd(&bins[(unsigned)((k0 >> 45) & 1023)], 1u);
        if (q1) atomicAdd(&bins[(unsigned)((k1 >> 45) & 1023)], 1u);
        __syncthreads();
        int target = (stotv < TOPK) ? stotv : TOPK;
        hist_select(bins, dwlo, t, target, sB, sS);
        int MS = *sS, MB = *sB;
        if (MS > 0 && MS <= 512) {
            if (t < 512) cand[t] = 0ull;
            __syncthreads();
            if (q0 && (int)((k0 >> 45) & 1023) >= MB) cand[atomicAdd(sCnt, 1)] = k0;
            if (q1 && (int)((k1 >> 45) & 1023) >= MB) cand[atomicAdd(sCnt, 1)] = k1;
            __syncthreads();
            if (MS <= 128)      bitonicN_desc<128>(cand, t);
            else if (MS <= 256) bitonicN_desc<256>(cand, t);
            else                bitonicN_desc<512>(cand, t);
            if (t < TOPK) outk[t] = cand[t];
            __syncthreads();
        } else {
            mSel = false;
        }
    }
    if (!mSel) {
        sKeys[t] = q0 ? k0 : 0ull;
        sKeys[t + 1024] = q1 ? k1 : 0ull;
        __syncthreads();
        bitonicN_desc<2048>(sKeys, t);
        if (t < TOPK) outk[t] = sKeys[t];
        __syncthreads();
    }

    // degenerate fallback: fewer than TOPK kept -> -inf entries, lowest
    // non-kept flat index first (matches lax.top_k over the masked matrix)
    if (t == 0 && stotv < TOPK) {
        int fill = stotv;
        int flat = 0;
        while (fill < TOPK) {
            int cc = flat >> 11;
            int n = scnt[cc];
            bool is_kept = false;
            for (int q = 0; q < n; q++) {
                unsigned int f2 = 0xFFFFFFFFu -
                    (unsigned int)(g_kept[cc * TOPK + q] & 0xFFFFFFFFull);
                if ((int)f2 == flat) { is_kept = true; break; }
            }
            if (!is_kept) {
                outk[fill] = ((unsigned long long)fkey(NEG_INF) << 32) |
                             (unsigned long long)(0xFFFFFFFFu - (unsigned)flat);
                fill++;
            }
            flat++;
        }
    }
    __syncthreads();

    if (t < TOPK) {
        unsigned long long key = outk[t];
        unsigned int flat = 0xFFFFFFFFu - (unsigned int)(key & 0xFFFFFFFFull);
        float sc = fkey_inv((unsigned int)(key >> 32));
        int cls = (int)(flat >> 11);      // R = 2048 = 2^11
        int rr  = (int)(flat & 2047u);
        float4 b4 = ((const float4*)boxes)[rr];
        out[t] = sc;
        out[TOPK + t * 4 + 0] = fminf(fmaxf(b4.x, 0.0f), IMGW);
        out[TOPK + t * 4 + 1] = fminf(fmaxf(b4.y, 0.0f), IMGH);
        out[TOPK + t * 4 + 2] = fminf(fmaxf(b4.z, 0.0f), IMGW);
        out[TOPK + t * 4 + 3] = fminf(fmaxf(b4.w, 0.0f), IMGH);
        out[TOPK + TOPK * 4 + t]        = (float)cls;
        out[TOPK + TOPK * 4 + TOPK + t] = (float)rr;
    }
}

extern "C" void kernel_launch(void* const* d_in, const int* in_sizes, int n_in,
                              void* d_out, int out_size)
{
    const float* boxes  = (const float*)d_in[0];   // [2048,4]
    const float* scores = (const float*)d_in[1];   // [2048,21]
    float* out = (float*)d_out;

    cudaFuncSetAttribute(fused_nms_kernel,
                         cudaFuncAttributeMaxDynamicSharedMemorySize, SMEM_BYTES);
    fused_nms_kernel<<<KCLS, 1024, SMEM_BYTES>>>(boxes, scores, out);
}

// round 11
// speedup vs baseline: 15.9313x; 2.2308x over previous
#include <cuda_runtime.h>
#include <math.h>
#include <stdint.h>

#define R        2048
#define KCLS     20
#define NSC      21
#define IMGW     1333.0f
#define IMGH     800.0f
#define SCORE_TH 0.5f
#define NMS_TH   0.5f
#define TOPK     100
#define KEPT_CAP 192
#define SEL_TGT  160
#define NEG_INF  __int_as_float(0xFF800000)

// ---------------- global scratch (tiny) ----------------
__device__ unsigned long long g_kept[KCLS * TOPK];  // merged keys per class, desc
__device__ int                g_kcnt[KCLS];
__device__ int                g_done = 0;

__device__ __forceinline__ unsigned int fkey(float f) {
    unsigned int u = __float_as_uint(f);
    return (u & 0x80000000u) ? ~u : (u | 0x80000000u);
}
__device__ __forceinline__ float fkey_inv(unsigned int k) {
    unsigned int bits = (k & 0x80000000u) ? (k ^ 0x80000000u) : ~k;
    return __uint_as_float(bits);
}

// ---------------- shared memory layout (dynamic) ----------------
#define OFF_SKEY   0          // u64[2048]   16384
#define OFF_SBOX   16384      // f32[4*2048] 32768
#define OFF_SAREA  49152      // f32[2048]    8192
#define OFF_KEPT   57344      // 5 * f32[192] 3840
#define OFF_FLAGS  61184      // u32[64]       256
#define OFF_DWLO   61440      // u32[64]       256  (also hist scratch)
#define OFF_DWHI   61696      // u32[64]       256
#define OFF_BAD    61952      // u32[64]       256
#define OFF_MISC   62208      // snk,sMerge,sB,sS,sCnt  32
#define OFF_BINS   62240      // u32[1024]    4096
#define OFF_CAND   66336      // u64[512]     4096
#define SMEM_BYTES 70432
// merge reuse: sKeys u64[2048]@0, outk u64[100]@16384, scnt int[20]@17184

__device__ __forceinline__ float iou_gt(float x1, float y1, float x2, float y2,
                                        float a, float cx1, float cy1,
                                        float cx2, float cy2, float ca) {
    float xx1 = fmaxf(x1, cx1);
    float yy1 = fmaxf(y1, cy1);
    float xx2 = fminf(x2, cx2);
    float yy2 = fminf(y2, cy2);
    float w = fmaxf(xx2 - xx1, 0.0f);
    float h = fmaxf(yy2 - yy1, 0.0f);
    float inter = w * h;
    float uni = a + ca - inter;
    return inter / fmaxf(uni, 1e-9f);
}

__device__ __forceinline__ unsigned long long shflxor64(unsigned long long v, int m) {
    unsigned int lo = (unsigned int)v, hi = (unsigned int)(v >> 32);
    lo = __shfl_xor_sync(0xFFFFFFFFu, lo, m);
    hi = __shfl_xor_sync(0xFFFFFFFFu, hi, m);
    return ((unsigned long long)hi << 32) | lo;
}

// N-element descending bitonic sort (N in {128,256,512,1024,2048}).
// Threads t < N/2 are active; all 1024 threads must call (block barriers).
template<int N>
__device__ __forceinline__ void bitonicN_desc(unsigned long long* a, int t)
{
    const int H = N >> 1;
    const bool act = (t < H);
    if (act) {
        unsigned long long v0 = a[t], v1 = a[t | H];
        #pragma unroll
        for (unsigned int kk = 2; kk <= 32; kk <<= 1) {
            bool d = ((t & kk) == 0);
            #pragma unroll
            for (unsigned int j = kk >> 1; j >= 1; j >>= 1) {
                unsigned long long o0 = __shfl_xor_sync(0xFFFFFFFFu, v0, j);
                unsigned long long o1 = __shfl_xor_sync(0xFFFFFFFFu, v1, j);
                bool up = ((t & j) == 0);
                v0 = (d == up) ? (v0 > o0 ? v0 : o0) : (v0 < o0 ? v0 : o0);
                v1 = (d == up) ? (v1 > o1 ? v1 : o1) : (v1 < o1 ? v1 : o1);
            }
        }
        a[t] = v0; a[t | H] = v1;
    }
    __syncthreads();

    for (unsigned int kk = 64; kk <= (unsigned int)N; kk <<= 1) {
        unsigned int j = kk >> 1;
        if (kk == (unsigned int)N) {
            if (act) {
                unsigned long long x = a[t], y = a[t | H];
                a[t]     = (x > y) ? x : y;
                a[t | H] = (x > y) ? y : x;
            }
            __syncthreads();
            j = (unsigned int)(H >> 1);
        }
        for (; j >= 32; j >>= 1) {
            if (act) {
                #pragma unroll
                for (int e = 0; e < 2; e++) {
                    unsigned int i = (unsigned int)t + (unsigned int)(e * H);
                    unsigned int ixj = i ^ j;
                    if (ixj > i) {
                        unsigned long long x = a[i], y = a[ixj];
                        bool descBlock = ((i & kk) == 0);
                        if (descBlock ? (x < y) : (x > y)) { a[i] = y; a[ixj] = x; }
                    }
                }
            }
            __syncthreads();
        }
        if (act) {
            unsigned long long v0 = a[t], v1 = a[t | H];
            bool d0 = (((unsigned)t & kk) == 0);
            bool d1 = ((((unsigned)t | (unsigned)H) & kk) == 0);
            #pragma unroll
            for (unsigned int jj = 16; jj >= 1; jj >>= 1) {
                unsigned long long o0 = __shfl_xor_sync(0xFFFFFFFFu, v0, jj);
                unsigned long long o1 = __shfl_xor_sync(0xFFFFFFFFu, v1, jj);
                bool up = (((unsigned)t & jj) == 0);
                v0 = (d0 == up) ? (v0 > o0 ? v0 : o0) : (v0 < o0 ? v0 : o0);
                v1 = (d1 == up) ? (v1 > o1 ? v1 : o1) : (v1 < o1 ? v1 : o1);
            }
            a[t] = v0; a[t | H] = v1;
        }
        __syncthreads();
    }
}

// Given bins[1024], find largest bin B with suffix-count >= target.
__device__ __forceinline__ void hist_select(const unsigned int* bins,
                                            unsigned int* scratch, int t,
                                            int target, int* sB, int* sS)
{
    const int lane = t & 31, w = t >> 5;
    unsigned int v = bins[t];
    #pragma unroll
    for (int d = 1; d < 32; d <<= 1) {
        unsigned int o = __shfl_down_sync(0xFFFFFFFFu, v, d);
        if (lane + d < 32) v += o;
    }
    if (lane == 0) scratch[w] = v;
    __syncthreads();
    if (t < 32) {
        unsigned int wv = scratch[t];
        #pragma unroll
        for (int d = 1; d < 32; d <<= 1) {
            unsigned int o = __shfl_down_sync(0xFFFFFFFFu, wv, d);
            if (t + d < 32) wv += o;
        }
        scratch[32 + t] = wv;
    }
    __syncthreads();
    unsigned int suf  = v + ((w < 31) ? scratch[32 + w + 1] : 0u);
    unsigned int sufn = suf - bins[t];
    if ((int)suf >= target && (int)sufn < target) { *sB = t; *sS = (int)suf; }
    __syncthreads();
}

__global__ void __launch_bounds__(1024, 1)
fused_nms_kernel(const float* __restrict__ boxes,
                 const float* __restrict__ scores,
                 float* __restrict__ out)
{
    extern __shared__ unsigned char smem[];
    unsigned long long* skey = (unsigned long long*)(smem + OFF_SKEY);
    float* sx1   = (float*)(smem + OFF_SBOX);
    float* sy1   = sx1 + R;
    float* sx2   = sy1 + R;
    float* sy2   = sx2 + R;
    float* sarea = (float*)(smem + OFF_SAREA);
    float* kx1   = (float*)(smem + OFF_KEPT);
    float* ky1   = kx1 + KEPT_CAP;
    float* kx2   = ky1 + KEPT_CAP;
    float* ky2   = kx2 + KEPT_CAP;
    float* karea = ky2 + KEPT_CAP;
    unsigned int* sflags  = (unsigned int*)(smem + OFF_FLAGS);
    unsigned int* dwlo    = (unsigned int*)(smem + OFF_DWLO);
    unsigned int* dwhi    = (unsigned int*)(smem + OFF_DWHI);
    unsigned int* sbad    = (unsigned int*)(smem + OFF_BAD);
    unsigned int* bins    = (unsigned int*)(smem + OFF_BINS);
    unsigned long long* cand = (unsigned long long*)(smem + OFF_CAND);
    int* snk    = (int*)(smem + OFF_MISC);
    int* sMerge = (int*)(smem + OFF_MISC + 4);
    int* sB     = (int*)(smem + OFF_MISC + 8);
    int* sS     = (int*)(smem + OFF_MISC + 12);
    int* sCnt   = (int*)(smem + OFF_MISC + 16);

    const int c    = blockIdx.x;
    const int t    = threadIdx.x;
    const int lane = t & 31;
    const int wid  = t >> 5;

    if (t < 64) sbad[t] = 0u;
    __syncthreads();

    // ---- phase 1a: vectorized score-finiteness scan (rare-bad bitmap) ----
    {
        const float4* s4 = (const float4*)scores;
        const int n4 = (R * NSC) / 4;
        for (int i = t; i < n4; i += 1024) {
            float4 f = s4[i];
            bool b0 = !isfinite(f.x), b1 = !isfinite(f.y);
            bool b2 = !isfinite(f.z), b3 = !isfinite(f.w);
            if (b0 | b1 | b2 | b3) {
                int e = 4 * i;
                if (b0) { unsigned rr = (unsigned)(e    ) / NSC; atomicOr(&sbad[rr >> 5], 1u << (rr & 31)); }
                if (b1) { unsigned rr = (unsigned)(e + 1) / NSC; atomicOr(&sbad[rr >> 5], 1u << (rr & 31)); }
                if (b2) { unsigned rr = (unsigned)(e + 2) / NSC; atomicOr(&sbad[rr >> 5], 1u << (rr & 31)); }
                if (b3) { unsigned rr = (unsigned)(e + 3) / NSC; atomicOr(&sbad[rr >> 5], 1u << (rr & 31)); }
            }
        }
    }
    __syncthreads();

    // ---- phase 1b: keys (0 for invalid -> sink) + valid count ----
    unsigned long long key0, key1;
    bool v0f, v1f;
    {
        int r0 = t;
        float4 b4 = ((const float4*)boxes)[r0];
        bool fin = isfinite(b4.x) && isfinite(b4.y) && isfinite(b4.z) && isfinite(b4.w);
        fin &= ((sbad[r0 >> 5] >> (r0 & 31)) & 1u) == 0u;
        float s = scores[r0 * NSC + c];
        v0f = fin && (s > SCORE_TH);
        key0 = v0f ? (((unsigned long long)fkey(s) << 32) |
                      (unsigned long long)(0xFFFFFFFFu - (unsigned)r0)) : 0ull;
        skey[r0] = key0;
        int r1 = t + 1024;
        float4 c4 = ((const float4*)boxes)[r1];
        bool fin1 = isfinite(c4.x) && isfinite(c4.y) && isfinite(c4.z) && isfinite(c4.w);
        fin1 &= ((sbad[r1 >> 5] >> (r1 & 31)) & 1u) == 0u;
        float s1 = scores[r1 * NSC + c];
        v1f = fin1 && (s1 > SCORE_TH);
        key1 = v1f ? (((unsigned long long)fkey(s1) << 32) |
                      (unsigned long long)(0xFFFFFFFFu - (unsigned)r1)) : 0ull;
        skey[r1] = key1;
    }
    const int V = __syncthreads_count(v0f) + __syncthreads_count(v1f);

    // ---- phase 2: exact top-S selection (monotone-bin histogram) ----
    bool okb = (key0 == 0ull || (key0 >> 55) == 0x17Eull) &&
               (key1 == 0ull || (key1 >> 55) == 0x17Eull);
    int nok = __syncthreads_count(okb);
    bool selOK = (nok == 1024) && (V > 0);
    int S = 0, B = 1024;
    if (selOK) {
        bins[t] = 0u;
        if (t == 0) { *sB = 1024; *sS = 0; *sCnt = 0; }
        __syncthreads();
        if (key0) atomicAdd(&bins[(unsigned)((key0 >> 45) & 1023)], 1u);
        if (key1) atomicAdd(&bins[(unsigned)((key1 >> 45) & 1023)], 1u);
        __syncthreads();
        int target = (V < SEL_TGT) ? V : SEL_TGT;
        hist_select(bins, dwlo, t, target, sB, sS);
        S = *sS; B = *sB;
        if (S > 0 && S <= 512) {
            if (t < 512) cand[t] = 0ull;
            __syncthreads();
            if (key0 && (int)((key0 >> 45) & 1023) >= B) cand[atomicAdd(sCnt, 1)] = key0;
            if (key1 && (int)((key1 >> 45) & 1023) >= B) cand[atomicAdd(sCnt, 1)] = key1;
            __syncthreads();
            if (S <= 128)      bitonicN_desc<128>(cand, t);
            else if (S <= 256) bitonicN_desc<256>(cand, t);
            else               bitonicN_desc<512>(cand, t);
        } else {
            selOK = false;
        }
    }

    // ---- phases 3+4: gather + chunked NMS (retry with full sort if needed) ----
    int nk = 0;
    for (int attempt = 0; attempt < 2; attempt++) {
        const bool useSel = (attempt == 0) && selOK;
        const unsigned long long* ckey;
        int CV;
        if (useSel) { ckey = cand; CV = S; }
        else { bitonicN_desc<2048>(skey, t); ckey = skey; CV = V; }

        for (int i = t; i < CV; i += 1024) {
            unsigned long long key = ckey[i];
            unsigned int rr = 0xFFFFFFFFu - (unsigned int)(key & 0xFFFFFFFFull);
            float4 b4 = ((const float4*)boxes)[rr];
            float x1 = fminf(fmaxf(b4.x, 0.0f), IMGW);
            float y1 = fminf(fmaxf(b4.y, 0.0f), IMGH);
            float x2 = fminf(fmaxf(b4.z, 0.0f), IMGW);
            float y2 = fminf(fmaxf(b4.w, 0.0f), IMGH);
            sx1[i] = x1; sy1[i] = y1; sx2[i] = x2; sy2[i] = y2;
            sarea[i] = (x2 - x1) * (y2 - y1);
        }
        if (t == 0) *snk = 0;
        __syncthreads();
        nk = 0;

        const int wcap = (CV + 63) >> 6;
        for (int ch = 0; ch < wcap && nk < TOPK; ch++) {
            #pragma unroll
            for (int half = 0; half < 2; half++) {
                int cd = (ch << 6) + wid + (half << 5);
                float x1 = sx1[cd], y1 = sy1[cd];
                float x2 = sx2[cd], y2 = sy2[cd];
                float a = sarea[cd];
                bool loc = false;
                if (cd < CV) {
                    for (int m = lane; m < nk; m += 32)
                        loc |= (iou_gt(x1, y1, x2, y2, a,
                                       kx1[m], ky1[m], kx2[m], ky2[m], karea[m])
                                > NMS_TH);
                }
                bool sup = __any_sync(0xFFFFFFFFu, loc);
                if (lane == 0) sflags[wid + (half << 5)] = sup ? 1u : 0u;

                int c0 = (ch << 6) + lane;
                int c1 = c0 + 32;
                bool blo = iou_gt(x1, y1, x2, y2, a,
                                  sx1[c0], sy1[c0], sx2[c0], sy2[c0], sarea[c0]) > NMS_TH;
                bool bhi = iou_gt(x1, y1, x2, y2, a,
                                  sx1[c1], sy1[c1], sx2[c1], sy2[c1], sarea[c1]) > NMS_TH;
                unsigned int rlo = __ballot_sync(0xFFFFFFFFu, blo);
                unsigned int rhi = __ballot_sync(0xFFFFFFFFu, bhi);
                if (lane == 0) {
                    dwlo[wid + (half << 5)] = rlo;
                    dwhi[wid + (half << 5)] = rhi;
                }
            }
            __syncthreads();

            if (wid == 0) {
                unsigned int f0 = sflags[lane], f1 = sflags[32 + lane];
                unsigned int slo = __ballot_sync(0xFFFFFFFFu, f0 != 0u);
                unsigned int shi = __ballot_sync(0xFFFFFFFFu, f1 != 0u);
                unsigned long long suppressed =
                    ((unsigned long long)shi << 32) | (unsigned long long)slo;
                int rem = CV - (ch << 6);
                unsigned long long prefix =
                    (rem >= 64) ? ~0ull : ((1ull << rem) - 1ull);
                unsigned long long pend = prefix & ~suppressed;

                // diagonal rows, masked to strictly-higher bits (DAG)
                unsigned long long d0 = (unsigned long long)dwlo[lane] |
                                        ((unsigned long long)dwhi[lane] << 32);
                unsigned long long d1 = (unsigned long long)dwlo[32 + lane] |
                                        ((unsigned long long)dwhi[32 + lane] << 32);
                d0 &= (~0ull) << (lane + 1);                      // row = lane (<=31)
                d1 = (lane == 31) ? 0ull : (d1 & ((~0ull) << (lane + 33)));

                // fixed-point parallel greedy (converges <= DAG depth + 1)
                unsigned long long kept = pend;
                #pragma unroll 1
                for (int it = 0; it < 64 && kept; it++) {
                    unsigned long long contrib = 0ull;
                    if ((kept >> lane) & 1ull)        contrib  = d0;
                    if ((kept >> (32 + lane)) & 1ull) contrib |= d1;
                    #pragma unroll
                    for (int off = 16; off; off >>= 1)
                        contrib |= shflxor64(contrib, off);
                    unsigned long long nw = pend & ~contrib;
                    if (nw == kept) break;
                    kept = nw;
                }

                // parallel append: slot = popc of kept bits below b
                int total = __popcll(kept);
                #pragma unroll
                for (int hb = 0; hb < 2; hb++) {
                    int b = lane + (hb << 5);
                    if ((kept >> b) & 1ull) {
                        int rankb = __popcll(kept & ((1ull << b) - 1ull));
                        int jj = (ch << 6) + b;
                        int pos = nk + rankb;
                        kx1[pos] = sx1[jj]; ky1[pos] = sy1[jj];
                        kx2[pos] = sx2[jj]; ky2[pos] = sy2[jj];
                        karea[pos] = sarea[jj];
                        if (pos < TOPK) {
                            unsigned long long key = ckey[jj];
                            unsigned int rr = 0xFFFFFFFFu -
                                (unsigned int)(key & 0xFFFFFFFFull);
                            unsigned int flat = (unsigned)c * R + rr;
                            g_kept[c * TOPK + pos] =
                                (key & 0xFFFFFFFF00000000ull) |
                                (unsigned long long)(0xFFFFFFFFu - flat);
                        }
                    }
                }
                if (lane == 0) *snk = nk + total;
            }
            __syncthreads();
            nk = *snk;
        }
        if (nk >= TOPK || CV >= V || !useSel) break;
    }

    // ---- completion: last-finishing CTA performs the merge ----
    if (t == 0) {
        g_kcnt[c] = (nk > TOPK) ? TOPK : nk;
        __threadfence();
        int ticket = atomicAdd(&g_done, 1);
        *sMerge = (ticket == KCLS - 1) ? 1 : 0;
        if (*sMerge) g_done = 0;          // reset for next graph replay
    }
    __syncthreads();
    if (*sMerge == 0) return;
    __threadfence();                      // acquire: see all g_kept/g_kcnt

    // ================= merge (single CTA) =================
    unsigned long long* sKeys = (unsigned long long*)(smem + 0);      // [2048]
    unsigned long long* outk  = (unsigned long long*)(smem + 16384);  // [100]
    int* scnt = (int*)(smem + 17184);                                 // [20]
    __syncthreads();

    if (t < KCLS) scnt[t] = g_kcnt[t];
    __syncthreads();

    unsigned long long k0 = 0ull, k1 = 0ull;
    bool q0 = false, q1 = false;
    {
        int i0 = t;
        if (i0 < KCLS * TOPK) {
            int cc = i0 / TOPK, p = i0 % TOPK;
            if (p < scnt[cc]) { k0 = g_kept[i0]; q0 = true; }
        }
        int i1 = t + 1024;
        if (i1 < KCLS * TOPK) {
            int cc = i1 / TOPK, p = i1 % TOPK;
            if (p < scnt[cc]) { k1 = g_kept[i1]; q1 = true; }
        }
    }
    const int stotv = __syncthreads_count(q0) + __syncthreads_count(q1);
    bool mok = (!q0 || (k0 >> 55) == 0x17Eull) &&
               (!q1 || (k1 >> 55) == 0x17Eull);
    int mnok = __syncthreads_count(mok);
    bool mSel = (mnok == 1024) && (stotv > 0);
    if (mSel) {
        bins[t] = 0u;
        if (t == 0) { *sB = 1024; *sS = 0; *sCnt = 0; }
        __syncthreads();
        if (q0) atomicAdd(&bins[(unsigned)((k0 >> 45) & 1023)], 1u);
        if (q1) atomicAdd(&bins[(unsigned)((k1 >> 45) & 1023)], 1u);
        __syncthreads();
        int target = (stotv < TOPK) ? stotv : TOPK;
        hist_select(bins, dwlo, t, target, sB, sS);
        int MS = *sS, MB = *sB;
        if (MS > 0 && MS <= 512) {
            if (t < 512) cand[t] = 0ull;
            __syncthreads();
            if (q0 && (int)((k0 >> 45) & 1023) >= MB) cand[atomicAdd(sCnt, 1)] = k0;
            if (q1 && (int)((k1 >> 45) & 1023) >= MB) cand[atomicAdd(sCnt, 1)] = k1;
            __syncthreads();
            if (MS <= 128)      bitonicN_desc<128>(cand, t);
            else if (MS <= 256) bitonicN_desc<256>(cand, t);
            else                bitonicN_desc<512>(cand, t);
            if (t < TOPK) outk[t] = cand[t];
            __syncthreads();
        } else {
            mSel = false;
        }
    }
    if (!mSel) {
        sKeys[t] = q0 ? k0 : 0ull;
        sKeys[t + 1024] = q1 ? k1 : 0ull;
        __syncthreads();
        bitonicN_desc<2048>(sKeys, t);
        if (t < TOPK) outk[t] = sKeys[t];
        __syncthreads();
    }

    // degenerate fallback: fewer than TOPK kept -> -inf entries, lowest
    // non-kept flat index first (matches lax.top_k over the masked matrix)
    if (t == 0 && stotv < TOPK) {
        int fill = stotv;
        int flat = 0;
        while (fill < TOPK) {
            int cc = flat >> 11;
            int n = scnt[cc];
            bool is_kept = false;
            for (int q = 0; q < n; q++) {
                unsigned int f2 = 0xFFFFFFFFu -
                    (unsigned int)(g_kept[cc * TOPK + q] & 0xFFFFFFFFull);
                if ((int)f2 == flat) { is_kept = true; break; }
            }
            if (!is_kept) {
                outk[fill] = ((unsigned long long)fkey(NEG_INF) << 32) |
                             (unsigned long long)(0xFFFFFFFFu - (unsigned)flat);
                fill++;
            }
            flat++;
        }
    }
    __syncthreads();

    if (t < TOPK) {
        unsigned long long key = outk[t];
        unsigned int flat = 0xFFFFFFFFu - (unsigned int)(key & 0xFFFFFFFFull);
        float sc = fkey_inv((unsigned int)(key >> 32));
        int cls = (int)(flat >> 11);      // R = 2048 = 2^11
        int rr  = (int)(flat & 2047u);
        float4 b4 = ((const float4*)boxes)[rr];
        out[t] = sc;
        out[TOPK + t * 4 + 0] = fminf(fmaxf(b4.x, 0.0f), IMGW);
        out[TOPK + t * 4 + 1] = fminf(fmaxf(b4.y, 0.0f), IMGH);
        out[TOPK + t * 4 + 2] = fminf(fmaxf(b4.z, 0.0f), IMGW);
        out[TOPK + t * 4 + 3] = fminf(fmaxf(b4.w, 0.0f), IMGH);
        out[TOPK + TOPK * 4 + t]        = (float)cls;
        out[TOPK + TOPK * 4 + TOPK + t] = (float)rr;
    }
}

extern "C" void kernel_launch(void* const* d_in, const int* in_sizes, int n_in,
                              void* d_out, int out_size)
{
    const float* boxes  = (const float*)d_in[0];   // [2048,4]
    const float* scores = (const float*)d_in[1];   // [2048,21]
    float* out = (float*)d_out;

    cudaFuncSetAttribute(fused_nms_kernel,
                         cudaFuncAttributeMaxDynamicSharedMemorySize, SMEM_BYTES);
    fused_nms_kernel<<<KCLS, 1024, SMEM_BYTES>>>(boxes, scores, out);
}